// round 3
// baseline (speedup 1.0000x reference)
#include <cuda_runtime.h>
#include <cmath>

// ---------------------------------------------------------------------------
// DecoderBlock: B=4, S=2048, D=1024, M=4096, fp32 in/out.
//   Q = x@Wq^T+bq ; K,V same                      [8192,1024] each
//   scores = QK^T/32 (causal) ; P = softmax       [4][2048,2048]
//   attn = P@V                                    [8192,1024]
//   O = attn@Wo^T+bo                              [8192,1024]
//   out = gelu(O@Wf^T+bf)                         [8192,4096]
// All GEMMs on tf32 mma.sync.m16n8k8 with rna-rounded inputs (fp32 accum).
// Static shared memory only (<48KB) — no cudaFuncSetAttribute, no dynamic smem.
// ---------------------------------------------------------------------------

#define BM 128
#define BN 128
#define BKT 16
#define NTHREADS 256

// Scratch (device globals: allocation-free per harness rules)
__device__ float g_Q[8192 * 1024];
__device__ float g_K[8192 * 1024];
__device__ float g_V[8192 * 1024];
__device__ float g_P[4 * 2048 * 2048];
__device__ float g_Attn[8192 * 1024];
__device__ float g_O[8192 * 1024];

__device__ __forceinline__ float f2tf32(float x) {
    unsigned u;
    asm("cvt.rna.tf32.f32 %0, %1;" : "=r"(u) : "f"(x));
    return __uint_as_float(u);
}

__device__ __forceinline__ void mma8(float* c, const unsigned* a, const unsigned* b) {
    asm volatile(
        "mma.sync.aligned.m16n8k8.row.col.f32.tf32.tf32.f32 "
        "{%0,%1,%2,%3}, {%4,%5,%6,%7}, {%8,%9}, {%0,%1,%2,%3};\n"
        : "+f"(c[0]), "+f"(c[1]), "+f"(c[2]), "+f"(c[3])
        : "r"(a[0]), "r"(a[1]), "r"(a[2]), "r"(a[3]), "r"(b[0]), "r"(b[1]));
}

__device__ __forceinline__ float gelu_exact(float v) {
    return 0.5f * v * (1.0f + erff(v * 0.70710678118654752f));
}

// EPI: 0 = C = alpha*acc ; 1 = acc + bias[col] ; 2 = gelu(acc + bias[col])
// BKMAJ: true  -> B is [N,K] row-major (weights / K-matrix, "NT" GEMM)
//        false -> B is [K,N] row-major (V matrix, "NN" GEMM)
// CAUSAL: skip output blocks strictly above the diagonal (QK^T)
// LIMITK: restrict k-loop to <= end of this row-block (P@V with causal P)
template <int EPI, bool BKMAJ, bool CAUSAL, bool LIMITK>
__global__ void __launch_bounds__(NTHREADS) gemm_tf32(
    const float* __restrict__ A, const float* __restrict__ B,
    const float* __restrict__ bias, float* __restrict__ C,
    int M, int N, int K, int lda, int ldb, int ldc,
    size_t strA, size_t strB, size_t strC, float alpha)
{
    constexpr int SA = BM + 1;                       // 129: k-major A, conflict-friendly
    constexpr int SB = BKMAJ ? (BN + 1) : (BN + 4);  // 129 (scalar sts) / 132 (float4 sts)

    __shared__ float As[2 * BKT * SA];
    __shared__ float Bs[2 * BKT * SB];

    const int bm = blockIdx.y, bn = blockIdx.x;
    if (CAUSAL && bn * BN > bm * BM + (BM - 1)) return;
    A += strA * blockIdx.z;
    B += strB * blockIdx.z;
    C += strC * blockIdx.z;
    const int kEnd = LIMITK ? min(K, bm * BM + BM) : K;
    const int nT = kEnd / BKT;

    const int tid = threadIdx.x;
    const int warp = tid >> 5, lane = tid & 31;
    const int wm = warp & 1, wn = warp >> 1;   // warp grid 2 (M) x 4 (N), tile 64x32
    const int gid = lane >> 2, tig = lane & 3;

    // global-load geometry: per buffer 128x16 A floats = 2 float4 / thread
    const int arow = tid >> 2;            // 0..63, + i*64
    const int acol4 = (tid & 3) * 4;      // 0..12
    const float* Ag = A + (size_t)(bm * BM + arow) * lda + acol4;

    int brow, bcol4;
    const float* Bg;
    if (BKMAJ) {
        brow = tid >> 2; bcol4 = (tid & 3) * 4;
        Bg = B + (size_t)(bn * BN + brow) * ldb + bcol4;
    } else {
        brow = tid >> 5; bcol4 = (tid & 31) * 4;   // 16 k-rows x 128 n-cols
        Bg = B + (size_t)brow * ldb + bn * BN + bcol4;
    }

    float acc[4][4][4];
#pragma unroll
    for (int i = 0; i < 4; i++)
#pragma unroll
        for (int j = 0; j < 4; j++)
#pragma unroll
            for (int k = 0; k < 4; k++) acc[i][j][k] = 0.f;

    float4 pa[2], pb[2];

    auto ldgAB = [&](int k0) {
#pragma unroll
        for (int i = 0; i < 2; i++)
            pa[i] = *(const float4*)(Ag + (size_t)(i * 64) * lda + k0);
        if (BKMAJ) {
#pragma unroll
            for (int i = 0; i < 2; i++)
                pb[i] = *(const float4*)(Bg + (size_t)(i * 64) * ldb + k0);
        } else {
#pragma unroll
            for (int i = 0; i < 2; i++)
                pb[i] = *(const float4*)(Bg + (size_t)(k0 + i * 8) * ldb);
        }
    };
    auto stsAB = [&](int buf) {
        float* da = As + buf * BKT * SA;
#pragma unroll
        for (int i = 0; i < 2; i++) {
            int r = arow + i * 64;
            da[(acol4 + 0) * SA + r] = f2tf32(pa[i].x);
            da[(acol4 + 1) * SA + r] = f2tf32(pa[i].y);
            da[(acol4 + 2) * SA + r] = f2tf32(pa[i].z);
            da[(acol4 + 3) * SA + r] = f2tf32(pa[i].w);
        }
        float* db = Bs + buf * BKT * SB;
        if (BKMAJ) {
#pragma unroll
            for (int i = 0; i < 2; i++) {
                int r = brow + i * 64;
                db[(bcol4 + 0) * SB + r] = f2tf32(pb[i].x);
                db[(bcol4 + 1) * SB + r] = f2tf32(pb[i].y);
                db[(bcol4 + 2) * SB + r] = f2tf32(pb[i].z);
                db[(bcol4 + 3) * SB + r] = f2tf32(pb[i].w);
            }
        } else {
#pragma unroll
            for (int i = 0; i < 2; i++) {
                float4 v;
                v.x = f2tf32(pb[i].x); v.y = f2tf32(pb[i].y);
                v.z = f2tf32(pb[i].z); v.w = f2tf32(pb[i].w);
                *(float4*)(db + (brow + i * 8) * SB + bcol4) = v;
            }
        }
    };

    ldgAB(0);
    stsAB(0);
    __syncthreads();

    for (int t = 0; t < nT; ++t) {
        const int buf = t & 1;
        if (t + 1 < nT) ldgAB((t + 1) * BKT);

        const float* a_s = As + buf * BKT * SA;
        const float* b_s = Bs + buf * BKT * SB;
#pragma unroll
        for (int kk = 0; kk < BKT; kk += 8) {
            unsigned af[4][4], bfr[4][2];
#pragma unroll
            for (int im = 0; im < 4; im++) {
                int m0 = wm * 64 + im * 16 + gid;
                af[im][0] = __float_as_uint(a_s[(kk + tig) * SA + m0]);
                af[im][1] = __float_as_uint(a_s[(kk + tig) * SA + m0 + 8]);
                af[im][2] = __float_as_uint(a_s[(kk + tig + 4) * SA + m0]);
                af[im][3] = __float_as_uint(a_s[(kk + tig + 4) * SA + m0 + 8]);
            }
#pragma unroll
            for (int in = 0; in < 4; in++) {
                int n0 = wn * 32 + in * 8 + gid;
                bfr[in][0] = __float_as_uint(b_s[(kk + tig) * SB + n0]);
                bfr[in][1] = __float_as_uint(b_s[(kk + tig + 4) * SB + n0]);
            }
#pragma unroll
            for (int im = 0; im < 4; im++)
#pragma unroll
                for (int in = 0; in < 4; in++)
                    mma8(acc[im][in], af[im], bfr[in]);
        }
        if (t + 1 < nT) {
            stsAB(buf ^ 1);
            __syncthreads();
        }
    }

    // epilogue
#pragma unroll
    for (int im = 0; im < 4; im++) {
        const int r0 = bm * BM + wm * 64 + im * 16 + gid;
#pragma unroll
        for (int in = 0; in < 4; in++) {
            const int c0 = bn * BN + wn * 32 + in * 8 + tig * 2;
            float v00 = acc[im][in][0], v01 = acc[im][in][1];
            float v10 = acc[im][in][2], v11 = acc[im][in][3];
            if (EPI == 0) {
                v00 *= alpha; v01 *= alpha; v10 *= alpha; v11 *= alpha;
            } else {
                const float b0 = bias[c0], b1 = bias[c0 + 1];
                v00 += b0; v01 += b1; v10 += b0; v11 += b1;
                if (EPI == 2) {
                    v00 = gelu_exact(v00); v01 = gelu_exact(v01);
                    v10 = gelu_exact(v10); v11 = gelu_exact(v11);
                }
            }
            *(float2*)(C + (size_t)r0 * ldc + c0) = make_float2(v00, v01);
            *(float2*)(C + (size_t)(r0 + 8) * ldc + c0) = make_float2(v10, v11);
        }
    }
}

// Row-wise causal softmax over P[b][q][0..q]; zero-fills (q, len).
__global__ void softmax_causal(float* __restrict__ P, int len) {
    const int q = blockIdx.x, b = blockIdx.y;
    float* row = P + ((size_t)b * len + q) * (size_t)len;
    const int n = q + 1;
    const int tid = threadIdx.x;

    __shared__ float red[32];

    float m = -3.4e38f;
    for (int i = tid; i < n; i += NTHREADS) m = fmaxf(m, row[i]);
#pragma unroll
    for (int o = 16; o; o >>= 1) m = fmaxf(m, __shfl_xor_sync(0xffffffff, m, o));
    if ((tid & 31) == 0) red[tid >> 5] = m;
    __syncthreads();
    if (tid == 0) {
        float v = -3.4e38f;
        for (int i = 0; i < NTHREADS / 32; i++) v = fmaxf(v, red[i]);
        red[0] = v;
    }
    __syncthreads();
    m = red[0];
    __syncthreads();

    float s = 0.f;
    for (int i = tid; i < n; i += NTHREADS) s += expf(row[i] - m);
#pragma unroll
    for (int o = 16; o; o >>= 1) s += __shfl_xor_sync(0xffffffff, s, o);
    if ((tid & 31) == 0) red[tid >> 5] = s;
    __syncthreads();
    if (tid == 0) {
        float v = 0.f;
        for (int i = 0; i < NTHREADS / 32; i++) v += red[i];
        red[0] = v;
    }
    __syncthreads();
    const float inv = 1.0f / red[0];

    for (int i = tid; i < n; i += NTHREADS) row[i] = expf(row[i] - m) * inv;
    for (int i = n + tid; i < len; i += NTHREADS) row[i] = 0.f;
}

extern "C" void kernel_launch(void* const* d_in, const int* in_sizes, int n_in,
                              void* d_out, int out_size)
{
    const float* x  = (const float*)d_in[0];
    const float* Wq = (const float*)d_in[1];
    const float* bq = (const float*)d_in[2];
    const float* Wk = (const float*)d_in[3];
    const float* bk = (const float*)d_in[4];
    const float* Wv = (const float*)d_in[5];
    const float* bv = (const float*)d_in[6];
    const float* Wo = (const float*)d_in[7];
    const float* bo = (const float*)d_in[8];
    const float* Wf = (const float*)d_in[9];
    const float* bff = (const float*)d_in[10];
    float* out = (float*)d_out;

    float *dQ, *dK, *dV, *dP, *dA, *dO;
    cudaGetSymbolAddress((void**)&dQ, g_Q);
    cudaGetSymbolAddress((void**)&dK, g_K);
    cudaGetSymbolAddress((void**)&dV, g_V);
    cudaGetSymbolAddress((void**)&dP, g_P);
    cudaGetSymbolAddress((void**)&dA, g_Attn);
    cudaGetSymbolAddress((void**)&dO, g_O);

    dim3 blk(NTHREADS);

    // Q/K/V projections: [8192,1024] x [1024,1024]^T + bias
    dim3 gProj(1024 / BN, 8192 / BM, 1);
    gemm_tf32<1, true, false, false><<<gProj, blk>>>(
        x, Wq, bq, dQ, 8192, 1024, 1024, 1024, 1024, 1024, 0, 0, 0, 1.f);
    gemm_tf32<1, true, false, false><<<gProj, blk>>>(
        x, Wk, bk, dK, 8192, 1024, 1024, 1024, 1024, 1024, 0, 0, 0, 1.f);
    gemm_tf32<1, true, false, false><<<gProj, blk>>>(
        x, Wv, bv, dV, 8192, 1024, 1024, 1024, 1024, 1024, 0, 0, 0, 1.f);

    // scores = Q K^T / sqrt(1024), causal block skip, batched over 4
    dim3 gS(2048 / BN, 2048 / BM, 4);
    gemm_tf32<0, true, true, false><<<gS, blk>>>(
        dQ, dK, nullptr, dP, 2048, 2048, 1024, 1024, 1024, 2048,
        (size_t)2048 * 1024, (size_t)2048 * 1024, (size_t)2048 * 2048, 0.03125f);

    // causal softmax (also zero-fills upper triangle)
    softmax_causal<<<dim3(2048, 4), blk>>>(dP, 2048);

    // attn = P @ V  (NN layout, k limited to row-block end)
    dim3 gA(1024 / BN, 2048 / BM, 4);
    gemm_tf32<0, false, false, true><<<gA, blk>>>(
        dP, dV, nullptr, dA, 2048, 1024, 2048, 2048, 1024, 1024,
        (size_t)2048 * 2048, (size_t)2048 * 1024, (size_t)2048 * 1024, 1.f);

    // O projection
    gemm_tf32<1, true, false, false><<<gProj, blk>>>(
        dA, Wo, bo, dO, 8192, 1024, 1024, 1024, 1024, 1024, 0, 0, 0, 1.f);

    // FFN + exact GELU -> d_out [8192, 4096]
    dim3 gF(4096 / BN, 8192 / BM, 1);
    gemm_tf32<2, true, false, false><<<gF, blk>>>(
        dO, Wf, bff, out, 8192, 4096, 1024, 1024, 1024, 4096, 0, 0, 0, 1.f);
}

// round 9
// speedup vs baseline: 1.7438x; 1.7438x over previous
#include <cuda_runtime.h>
#include <cmath>

// ---------------------------------------------------------------------------
// DecoderBlock, sm_103 family target (no tcgen05): tf32 mma.sync.m16n8k8.
// Conflict-free smem layout: addr(r,k) = r*20 + (k&~3) + ((k&3)^(r&3)).
// V produced transposed (Vt) so P@V is the same NT GEMM with causal K-trim.
// ---------------------------------------------------------------------------

#define BM 128
#define BN 128
#define BKT 16
#define NTHREADS 256
#define RS 20                     // smem row stride in floats

__device__ float g_Q[8192 * 1024];
__device__ float g_K[8192 * 1024];
__device__ float g_Vt[1024 * 8192];
__device__ float g_P[4 * 2048 * 2048];
__device__ float g_Attn[8192 * 1024];
__device__ float g_O[8192 * 1024];

__device__ __forceinline__ float f2tf32(float x) {
    unsigned u;
    asm("cvt.rna.tf32.f32 %0, %1;" : "=r"(u) : "f"(x));
    return __uint_as_float(u);
}

__device__ __forceinline__ void mma8(float* c, const unsigned* a, const unsigned* b) {
    asm volatile(
        "mma.sync.aligned.m16n8k8.row.col.f32.tf32.tf32.f32 "
        "{%0,%1,%2,%3}, {%4,%5,%6,%7}, {%8,%9}, {%0,%1,%2,%3};\n"
        : "+f"(c[0]), "+f"(c[1]), "+f"(c[2]), "+f"(c[3])
        : "r"(a[0]), "r"(a[1]), "r"(a[2]), "r"(a[3]), "r"(b[0]), "r"(b[1]));
}

__device__ __forceinline__ float gelu_exact(float v) {
    return 0.5f * v * (1.0f + erff(v * 0.70710678118654752f));
}

// EPI: 0 = alpha*acc ; 1 = acc+bias ; 2 = gelu(acc+bias) ; 3 = transposed acc+bias
// CAUSAL: skip tiles strictly above diagonal.  LIMITK: k-loop to row-block end.
// B is always [N,K] row-major.
template <int EPI, bool CAUSAL, bool LIMITK>
__global__ void __launch_bounds__(NTHREADS, 2) gemm_tf32(
    const float* __restrict__ A, const float* __restrict__ B,
    const float* __restrict__ bias, float* __restrict__ C,
    int K, int lda, int ldb, int ldc,
    long long strA, long long strB, long long strC, float alpha)
{
    __shared__ float As[2][BM * RS];
    __shared__ float Bs[2][BN * RS];

    const int bm = blockIdx.y, bn = blockIdx.x;
    if (CAUSAL && bn * BN > bm * BM + (BM - 1)) return;
    A += (long long)blockIdx.z * strA;
    B += (long long)blockIdx.z * strB;
    C += (long long)blockIdx.z * strC;
    const int nT = LIMITK ? (bm + 1) * (128 / BKT) : (K / BKT);

    const int tid = threadIdx.x;
    const int warp = tid >> 5, lane = tid & 31;
    const int wm = warp & 1, wn = warp >> 1;   // 2 x 4 warp grid, 64x32 warp tile
    const int g = lane >> 2, tig = lane & 3;
    const int tx = tig ^ (g & 3);              // swizzled k offset for frag reads

    // global-load geometry: 4 lanes per row (16B each), rows r and r+64
    const int arow = tid >> 2;                 // 0..63
    const int ac4 = (tid & 3) * 4;             // 0,4,8,12
    const float* Ag = A + (size_t)(bm * BM + arow) * lda + ac4;
    const float* Bg = B + (size_t)(bn * BN + arow) * ldb + ac4;

    float acc[4][4][4];
#pragma unroll
    for (int i = 0; i < 4; i++)
#pragma unroll
        for (int j = 0; j < 4; j++)
#pragma unroll
            for (int k = 0; k < 4; k++) acc[i][j][k] = 0.f;

    float4 pa[2], pb[2];

#define LDG_AB(k0) do {                                                     \
    pa[0] = *(const float4*)(Ag + (k0));                                    \
    pa[1] = *(const float4*)(Ag + (size_t)64 * lda + (k0));                 \
    pb[0] = *(const float4*)(Bg + (k0));                                    \
    pb[1] = *(const float4*)(Bg + (size_t)64 * ldb + (k0));                 \
} while (0)

#define STS1(dst, v, r) do {                                                \
    float* _p = (dst) + (r) * RS + ac4;                                     \
    const int _rx = (r) & 3;                                                \
    _p[0 ^ _rx] = f2tf32((v).x);                                            \
    _p[1 ^ _rx] = f2tf32((v).y);                                            \
    _p[2 ^ _rx] = f2tf32((v).z);                                            \
    _p[3 ^ _rx] = f2tf32((v).w);                                            \
} while (0)

#define STS_AB(buf) do {                                                    \
    STS1(As[buf], pa[0], arow);                                             \
    STS1(As[buf], pa[1], arow + 64);                                        \
    STS1(Bs[buf], pb[0], arow);                                             \
    STS1(Bs[buf], pb[1], arow + 64);                                        \
} while (0)

    LDG_AB(0);
    STS_AB(0);
    __syncthreads();

    for (int t = 0; t < nT; ++t) {
        const int buf = t & 1;
        if (t + 1 < nT) LDG_AB((t + 1) * BKT);

        const float* a_s = As[buf];
        const float* b_s = Bs[buf];
#pragma unroll
        for (int kk = 0; kk < BKT; kk += 8) {
            unsigned af[4][4], bfr[4][2];
#pragma unroll
            for (int im = 0; im < 4; im++) {
                const int m0 = wm * 64 + im * 16 + g;
                const float* p0 = a_s + m0 * RS + kk + tx;
                af[im][0] = __float_as_uint(p0[0]);
                af[im][1] = __float_as_uint(p0[8 * RS]);
                af[im][2] = __float_as_uint(p0[4]);
                af[im][3] = __float_as_uint(p0[8 * RS + 4]);
            }
#pragma unroll
            for (int in = 0; in < 4; in++) {
                const int n0 = wn * 32 + in * 8 + g;
                const float* p0 = b_s + n0 * RS + kk + tx;
                bfr[in][0] = __float_as_uint(p0[0]);
                bfr[in][1] = __float_as_uint(p0[4]);
            }
#pragma unroll
            for (int im = 0; im < 4; im++)
#pragma unroll
                for (int in = 0; in < 4; in++)
                    mma8(acc[im][in], af[im], bfr[in]);
        }
        if (t + 1 < nT) {
            __syncthreads();
            STS_AB(buf ^ 1);
            __syncthreads();
        }
    }

    // epilogue
#pragma unroll
    for (int im = 0; im < 4; im++) {
        const int r0 = bm * BM + wm * 64 + im * 16 + g;
#pragma unroll
        for (int in = 0; in < 4; in++) {
            const int c0 = bn * BN + wn * 32 + in * 8 + tig * 2;
            float v00 = acc[im][in][0], v01 = acc[im][in][1];
            float v10 = acc[im][in][2], v11 = acc[im][in][3];
            if (EPI == 0) {
                v00 *= alpha; v01 *= alpha; v10 *= alpha; v11 *= alpha;
            } else {
                const float b0 = bias[c0], b1 = bias[c0 + 1];
                v00 += b0; v01 += b1; v10 += b0; v11 += b1;
                if (EPI == 2) {
                    v00 = gelu_exact(v00); v01 = gelu_exact(v01);
                    v10 = gelu_exact(v10); v11 = gelu_exact(v11);
                }
            }
            if (EPI == 3) {
                C[(size_t)c0 * ldc + r0] = v00;
                C[(size_t)(c0 + 1) * ldc + r0] = v01;
                C[(size_t)c0 * ldc + r0 + 8] = v10;
                C[(size_t)(c0 + 1) * ldc + r0 + 8] = v11;
            } else {
                *(float2*)(C + (size_t)r0 * ldc + c0) = make_float2(v00, v01);
                *(float2*)(C + (size_t)(r0 + 8) * ldc + c0) = make_float2(v10, v11);
            }
        }
    }
#undef LDG_AB
#undef STS1
#undef STS_AB
}

// Row-wise causal softmax; caches the row in smem; zero-fills only up to the
// 128-aligned block end (all that P@V's LIMITK ever reads).
__global__ void softmax_causal(float* __restrict__ P, int len) {
    __shared__ float buf[2048];
    __shared__ float red[33];
    const int q = blockIdx.x, b = blockIdx.y;
    float* row = P + ((size_t)b * len + q) * (size_t)len;
    const int n = q + 1;
    const int tid = threadIdx.x;

    float m = -3.4e38f;
    for (int i = tid; i < n; i += NTHREADS) { float v = row[i]; buf[i] = v; m = fmaxf(m, v); }
#pragma unroll
    for (int o = 16; o; o >>= 1) m = fmaxf(m, __shfl_xor_sync(0xffffffff, m, o));
    if ((tid & 31) == 0) red[tid >> 5] = m;
    __syncthreads();
    if (tid == 0) {
        float v = -3.4e38f;
        for (int i = 0; i < NTHREADS / 32; i++) v = fmaxf(v, red[i]);
        red[32] = v;
    }
    __syncthreads();
    m = red[32];

    float s = 0.f;
    for (int i = tid; i < n; i += NTHREADS) { float e = __expf(buf[i] - m); buf[i] = e; s += e; }
#pragma unroll
    for (int o = 16; o; o >>= 1) s += __shfl_xor_sync(0xffffffff, s, o);
    if ((tid & 31) == 0) red[tid >> 5] = s;
    __syncthreads();
    if (tid == 0) {
        float v = 0.f;
        for (int i = 0; i < NTHREADS / 32; i++) v += red[i];
        red[32] = 1.0f / v;
    }
    __syncthreads();
    const float inv = red[32];

    for (int i = tid; i < n; i += NTHREADS) row[i] = buf[i] * inv;
    const int zend = min(len, ((q >> 7) + 1) << 7);
    for (int i = n + tid; i < zend; i += NTHREADS) row[i] = 0.f;
}

extern "C" void kernel_launch(void* const* d_in, const int* in_sizes, int n_in,
                              void* d_out, int out_size)
{
    const float* x  = (const float*)d_in[0];
    const float* Wq = (const float*)d_in[1];
    const float* bq = (const float*)d_in[2];
    const float* Wk = (const float*)d_in[3];
    const float* bk = (const float*)d_in[4];
    const float* Wv = (const float*)d_in[5];
    const float* bv = (const float*)d_in[6];
    const float* Wo = (const float*)d_in[7];
    const float* bo = (const float*)d_in[8];
    const float* Wf = (const float*)d_in[9];
    const float* bff = (const float*)d_in[10];
    float* out = (float*)d_out;

    float *dQ, *dK, *dVt, *dP, *dA, *dO;
    cudaGetSymbolAddress((void**)&dQ, g_Q);
    cudaGetSymbolAddress((void**)&dK, g_K);
    cudaGetSymbolAddress((void**)&dVt, g_Vt);
    cudaGetSymbolAddress((void**)&dP, g_P);
    cudaGetSymbolAddress((void**)&dA, g_Attn);
    cudaGetSymbolAddress((void**)&dO, g_O);

    dim3 blk(NTHREADS);

    // Q, K projections: [8192,1024] @ W^T + b
    dim3 gProj(1024 / BN, 8192 / BM, 1);
    gemm_tf32<1, false, false><<<gProj, blk>>>(
        x, Wq, bq, dQ, 1024, 1024, 1024, 1024, 0, 0, 0, 1.f);
    gemm_tf32<1, false, false><<<gProj, blk>>>(
        x, Wk, bk, dK, 1024, 1024, 1024, 1024, 0, 0, 0, 1.f);
    // V projection stored transposed: Vt[1024][8192]
    gemm_tf32<3, false, false><<<gProj, blk>>>(
        x, Wv, bv, dVt, 1024, 1024, 1024, 8192, 0, 0, 0, 1.f);

    // scores = Q K^T / 32, causal tile skip, batched over 4
    dim3 gS(2048 / BN, 2048 / BM, 4);
    gemm_tf32<0, true, false><<<gS, blk>>>(
        dQ, dK, nullptr, dP, 1024, 1024, 1024, 2048,
        2048LL * 1024, 2048LL * 1024, 2048LL * 2048, 0.03125f);

    softmax_causal<<<dim3(2048, 4), blk>>>(dP, 2048);

    // attn = P @ Vt^T : A=[2048,2048] P, B=Vt rows=d (ldb=8192), batch via
    // column offset strB=2048; causal K-trim via LIMITK.
    dim3 gA(1024 / BN, 2048 / BM, 4);
    gemm_tf32<0, false, true><<<gA, blk>>>(
        dP, dVt, nullptr, dA, 2048, 2048, 8192, 1024,
        2048LL * 2048, 2048LL, 2048LL * 1024, 1.f);

    // O projection
    gemm_tf32<1, false, false><<<gProj, blk>>>(
        dA, Wo, bo, dO, 1024, 1024, 1024, 1024, 0, 0, 0, 1.f);

    // FFN + exact GELU -> d_out [8192, 4096]
    dim3 gF(4096 / BN, 8192 / BM, 1);
    gemm_tf32<2, false, false><<<gF, blk>>>(
        dO, Wf, bff, out, 1024, 1024, 1024, 4096, 0, 0, 0, 1.f);
}

// round 11
// speedup vs baseline: 2.5216x; 1.4460x over previous
#include <cuda_runtime.h>
#include <cmath>
#include <cstdint>

// ---------------------------------------------------------------------------
// DecoderBlock, sm_103 family: tf32 mma.sync.m16n8k8 with cp.async pipeline.
// All GEMM operands are PRE-ROUNDED to tf32 in gmem (producers round), so the
// mainloop is: cp.async 16B gmem->smem (SW128 swizzle), frag LDS, MMA.
// 3-stage ring, one __syncthreads per 32-k stage.
//   smem layout per stage: A[128 rows x 128B], B[128 x 128B]; element (r,k)
//   at byte r*128 + ((k>>2)^(r&7))*16 + (k&3)*4  (bank-conflict-free reads).
// ---------------------------------------------------------------------------

#define BM 128
#define BN 128
#define BKT 32
#define NTHREADS 256
#define STAGE_BYTES 32768           // A tile 16KB + B tile 16KB
#define SMEM_BYTES (3 * STAGE_BYTES)

__device__ float g_Q[8192 * 1024];
__device__ float g_K[8192 * 1024];
__device__ float g_Vt[1024 * 8192];
__device__ float g_P[4 * 2048 * 2048];
__device__ float g_Attn[8192 * 1024];
__device__ float g_O[8192 * 1024];
__device__ float g_Xr[8192 * 1024];     // rounded x
__device__ float g_Wr[8 * 1024 * 1024]; // rounded Wq,Wk,Wv,Wo (1M each), Wf (4M)

__device__ __forceinline__ float f2tf32(float x) {
    unsigned u;
    asm("cvt.rna.tf32.f32 %0, %1;" : "=r"(u) : "f"(x));
    return __uint_as_float(u);
}

__device__ __forceinline__ uint32_t s2u(const void* p) {
    uint32_t a;
    asm("{ .reg .u64 t; cvta.to.shared.u64 t, %1; cvt.u32.u64 %0, t; }"
        : "=r"(a) : "l"(p));
    return a;
}

__device__ __forceinline__ void mma8(float* c, const unsigned* a, const unsigned* b) {
    asm volatile(
        "mma.sync.aligned.m16n8k8.row.col.f32.tf32.tf32.f32 "
        "{%0,%1,%2,%3}, {%4,%5,%6,%7}, {%8,%9}, {%0,%1,%2,%3};\n"
        : "+f"(c[0]), "+f"(c[1]), "+f"(c[2]), "+f"(c[3])
        : "r"(a[0]), "r"(a[1]), "r"(a[2]), "r"(a[3]), "r"(b[0]), "r"(b[1]));
}

#define CP16(dst, src) \
    asm volatile("cp.async.cg.shared.global [%0], [%1], 16;" :: "r"(dst), "l"(src))
#define CP_COMMIT() asm volatile("cp.async.commit_group;")
#define CP_WAIT1() asm volatile("cp.async.wait_group 1;")
#define CP_WAIT0() asm volatile("cp.async.wait_group 0;")

__device__ __forceinline__ float gelu_exact(float v) {
    return 0.5f * v * (1.0f + erff(v * 0.70710678118654752f));
}

// EPI: 0 = alpha*acc ; 1 = acc+bias ; 2 = gelu(acc+bias) ; 3 = transposed acc+bias
// CAUSAL: skip tiles above diagonal.  LIMITK: k-loop to row-block end.
// RND: round outputs to tf32 (when consumed by a later GEMM).
// A [M,K] row-major, B [N,K] row-major; both pre-rounded tf32 values.
template <int EPI, bool CAUSAL, bool LIMITK, bool RND>
__global__ void __launch_bounds__(NTHREADS, 2) gemm_tf32(
    const float* __restrict__ A, const float* __restrict__ B,
    const float* __restrict__ bias, float* __restrict__ C,
    int K, int lda, int ldb, int ldc,
    long long strA, long long strB, long long strC, float alpha)
{
    extern __shared__ char smem[];
    const uint32_t sbase = s2u(smem);

    const int bm = blockIdx.y, bn = blockIdx.x;
    if (CAUSAL && bn * BN > bm * BM + (BM - 1)) return;
    A += (long long)blockIdx.z * strA;
    B += (long long)blockIdx.z * strB;
    C += (long long)blockIdx.z * strC;
    const int nT = LIMITK ? (bm + 1) * (128 / BKT) : (K / BKT);

    const int tid = threadIdx.x;
    const int warp = tid >> 5, lane = tid & 31;
    const int wm = warp & 1, wn = warp >> 2;   // reuse: warp grid 2(M) x 4(N)
    const int wn4 = (warp >> 1) & 3;           // 0..3 over N
    const int g = lane >> 2, tig = lane & 3;

    const float* Arow = A + (size_t)(bm * BM) * lda;
    const float* Brow = B + (size_t)(bn * BN) * ldb;

    float acc[4][4][4];
#pragma unroll
    for (int i = 0; i < 4; i++)
#pragma unroll
        for (int j = 0; j < 4; j++)
#pragma unroll
            for (int k = 0; k < 4; k++) acc[i][j][k] = 0.f;

    // cp.async of one stage: 1024 16B-groups per tile, 4 per thread per tile
    auto issue = [&](int t) {
        const int s = t % 3;
        const int k0 = t * BKT;
        const uint32_t dA = sbase + s * STAGE_BYTES;
        const uint32_t dB = dA + 16384;
#pragma unroll
        for (int i = 0; i < 4; i++) {
            const int gi = i * 256 + tid;       // 0..1023
            const int r = gi >> 3, j = gi & 7;
            const uint32_t off = r * 128 + ((j ^ (r & 7)) << 4);
            CP16(dA + off, Arow + (size_t)r * lda + k0 + j * 4);
            CP16(dB + off, Brow + (size_t)r * ldb + k0 + j * 4);
        }
        CP_COMMIT();
    };

    issue(0);
    if (nT > 1) issue(1);

    for (int t = 0; t < nT; ++t) {
        if (t < nT - 1) CP_WAIT1(); else CP_WAIT0();
        __syncthreads();
        if (t + 2 < nT) issue(t + 2);

        const float* a_s = (const float*)(smem + (t % 3) * STAGE_BYTES);
        const float* b_s = a_s + 4096;
#pragma unroll
        for (int kk = 0; kk < BKT; kk += 8) {
            const int j0 = kk >> 2;
            const int sw0 = ((j0 ^ g) << 2) + tig;  // float index within row
            const int sw1 = sw0 ^ 4;                // (j0+1)^g flips bit0 of j
            unsigned af[4][4], bfr[4][2];
#pragma unroll
            for (int im = 0; im < 4; im++) {
                const int m0 = wm * 64 + im * 16 + g;
                af[im][0] = __float_as_uint(a_s[m0 * 32 + sw0]);
                af[im][1] = __float_as_uint(a_s[(m0 + 8) * 32 + sw0]);
                af[im][2] = __float_as_uint(a_s[m0 * 32 + sw1]);
                af[im][3] = __float_as_uint(a_s[(m0 + 8) * 32 + sw1]);
            }
#pragma unroll
            for (int in = 0; in < 4; in++) {
                const int n0 = wn4 * 32 + in * 8 + g;
                bfr[in][0] = __float_as_uint(b_s[n0 * 32 + sw0]);
                bfr[in][1] = __float_as_uint(b_s[n0 * 32 + sw1]);
            }
#pragma unroll
            for (int im = 0; im < 4; im++)
#pragma unroll
                for (int in = 0; in < 4; in++)
                    mma8(acc[im][in], af[im], bfr[in]);
        }
        __syncthreads();   // all warps done reading stage t before t+3 overwrites
    }

    // epilogue
#pragma unroll
    for (int im = 0; im < 4; im++) {
        const int r0 = bm * BM + wm * 64 + im * 16 + g;
#pragma unroll
        for (int in = 0; in < 4; in++) {
            const int c0 = bn * BN + wn4 * 32 + in * 8 + tig * 2;
            float v00 = acc[im][in][0], v01 = acc[im][in][1];
            float v10 = acc[im][in][2], v11 = acc[im][in][3];
            if (EPI == 0) {
                v00 *= alpha; v01 *= alpha; v10 *= alpha; v11 *= alpha;
            } else {
                const float b0 = bias[c0], b1 = bias[c0 + 1];
                v00 += b0; v01 += b1; v10 += b0; v11 += b1;
                if (EPI == 2) {
                    v00 = gelu_exact(v00); v01 = gelu_exact(v01);
                    v10 = gelu_exact(v10); v11 = gelu_exact(v11);
                }
            }
            if (RND) {
                v00 = f2tf32(v00); v01 = f2tf32(v01);
                v10 = f2tf32(v10); v11 = f2tf32(v11);
            }
            if (EPI == 3) {
                C[(size_t)c0 * ldc + r0] = v00;
                C[(size_t)(c0 + 1) * ldc + r0] = v01;
                C[(size_t)c0 * ldc + r0 + 8] = v10;
                C[(size_t)(c0 + 1) * ldc + r0 + 8] = v11;
            } else {
                *(float2*)(C + (size_t)r0 * ldc + c0) = make_float2(v00, v01);
                *(float2*)(C + (size_t)(r0 + 8) * ldc + c0) = make_float2(v10, v11);
            }
        }
    }
}

// Elementwise tf32 rounding copy (for x and the weight matrices).
__global__ void round_copy(const float* __restrict__ in, float* __restrict__ out,
                           long long n4) {
    long long i = (long long)blockIdx.x * blockDim.x + threadIdx.x;
    long long stride = (long long)gridDim.x * blockDim.x;
    for (; i < n4; i += stride) {
        float4 v = ((const float4*)in)[i];
        v.x = f2tf32(v.x); v.y = f2tf32(v.y); v.z = f2tf32(v.z); v.w = f2tf32(v.w);
        ((float4*)out)[i] = v;
    }
}

// Row-wise causal softmax; rounds outputs to tf32; zero-fills to 128-block end.
__global__ void softmax_causal(float* __restrict__ P, int len) {
    __shared__ float buf[2048];
    __shared__ float red[33];
    const int q = blockIdx.x, b = blockIdx.y;
    float* row = P + ((size_t)b * len + q) * (size_t)len;
    const int n = q + 1;
    const int tid = threadIdx.x;

    float m = -3.4e38f;
    for (int i = tid; i < n; i += NTHREADS) { float v = row[i]; buf[i] = v; m = fmaxf(m, v); }
#pragma unroll
    for (int o = 16; o; o >>= 1) m = fmaxf(m, __shfl_xor_sync(0xffffffff, m, o));
    if ((tid & 31) == 0) red[tid >> 5] = m;
    __syncthreads();
    if (tid == 0) {
        float v = -3.4e38f;
        for (int i = 0; i < NTHREADS / 32; i++) v = fmaxf(v, red[i]);
        red[32] = v;
    }
    __syncthreads();
    m = red[32];

    float s = 0.f;
    for (int i = tid; i < n; i += NTHREADS) { float e = __expf(buf[i] - m); buf[i] = e; s += e; }
#pragma unroll
    for (int o = 16; o; o >>= 1) s += __shfl_xor_sync(0xffffffff, s, o);
    if ((tid & 31) == 0) red[tid >> 5] = s;
    __syncthreads();
    if (tid == 0) {
        float v = 0.f;
        for (int i = 0; i < NTHREADS / 32; i++) v += red[i];
        red[32] = 1.0f / v;
    }
    __syncthreads();
    const float inv = red[32];

    for (int i = tid; i < n; i += NTHREADS) row[i] = f2tf32(buf[i] * inv);
    const int zend = min(len, ((q >> 7) + 1) << 7);
    for (int i = n + tid; i < zend; i += NTHREADS) row[i] = 0.f;
}

extern "C" void kernel_launch(void* const* d_in, const int* in_sizes, int n_in,
                              void* d_out, int out_size)
{
    const float* x  = (const float*)d_in[0];
    const float* Wq = (const float*)d_in[1];
    const float* bq = (const float*)d_in[2];
    const float* Wk = (const float*)d_in[3];
    const float* bk = (const float*)d_in[4];
    const float* Wv = (const float*)d_in[5];
    const float* bv = (const float*)d_in[6];
    const float* Wo = (const float*)d_in[7];
    const float* bo = (const float*)d_in[8];
    const float* Wf = (const float*)d_in[9];
    const float* bff = (const float*)d_in[10];
    float* out = (float*)d_out;

    float *dQ, *dK, *dVt, *dP, *dA, *dO, *dXr, *dWr;
    cudaGetSymbolAddress((void**)&dQ, g_Q);
    cudaGetSymbolAddress((void**)&dK, g_K);
    cudaGetSymbolAddress((void**)&dVt, g_Vt);
    cudaGetSymbolAddress((void**)&dP, g_P);
    cudaGetSymbolAddress((void**)&dA, g_Attn);
    cudaGetSymbolAddress((void**)&dO, g_O);
    cudaGetSymbolAddress((void**)&dXr, g_Xr);
    cudaGetSymbolAddress((void**)&dWr, g_Wr);
    float* dWqr = dWr;
    float* dWkr = dWr + 1024 * 1024;
    float* dWvr = dWr + 2 * 1024 * 1024;
    float* dWor = dWr + 3 * 1024 * 1024;
    float* dWfr = dWr + 4 * 1024 * 1024;

    cudaFuncSetAttribute(gemm_tf32<1, false, false, true>,
                         cudaFuncAttributeMaxDynamicSharedMemorySize, SMEM_BYTES);
    cudaFuncSetAttribute(gemm_tf32<3, false, false, true>,
                         cudaFuncAttributeMaxDynamicSharedMemorySize, SMEM_BYTES);
    cudaFuncSetAttribute(gemm_tf32<0, true, false, false>,
                         cudaFuncAttributeMaxDynamicSharedMemorySize, SMEM_BYTES);
    cudaFuncSetAttribute(gemm_tf32<0, false, true, true>,
                         cudaFuncAttributeMaxDynamicSharedMemorySize, SMEM_BYTES);
    cudaFuncSetAttribute(gemm_tf32<2, false, false, false>,
                         cudaFuncAttributeMaxDynamicSharedMemorySize, SMEM_BYTES);

    dim3 blk(NTHREADS);

    // pre-round x and weights to tf32
    round_copy<<<256, 256>>>(x, dXr, 8192LL * 1024 / 4);
    round_copy<<<64, 256>>>(Wq, dWqr, 1024LL * 1024 / 4);
    round_copy<<<64, 256>>>(Wk, dWkr, 1024LL * 1024 / 4);
    round_copy<<<64, 256>>>(Wv, dWvr, 1024LL * 1024 / 4);
    round_copy<<<64, 256>>>(Wo, dWor, 1024LL * 1024 / 4);
    round_copy<<<128, 256>>>(Wf, dWfr, 4096LL * 1024 / 4);

    // Q, K projections (outputs rounded)
    dim3 gProj(1024 / BN, 8192 / BM, 1);
    gemm_tf32<1, false, false, true><<<gProj, blk, SMEM_BYTES>>>(
        dXr, dWqr, bq, dQ, 1024, 1024, 1024, 1024, 0, 0, 0, 1.f);
    gemm_tf32<1, false, false, true><<<gProj, blk, SMEM_BYTES>>>(
        dXr, dWkr, bk, dK, 1024, 1024, 1024, 1024, 0, 0, 0, 1.f);
    // V projection stored transposed + rounded: Vt[1024][8192]
    gemm_tf32<3, false, false, true><<<gProj, blk, SMEM_BYTES>>>(
        dXr, dWvr, bv, dVt, 1024, 1024, 1024, 8192, 0, 0, 0, 1.f);

    // scores = Q K^T / 32, causal tile skip (unrounded; softmax re-rounds)
    dim3 gS(2048 / BN, 2048 / BM, 4);
    gemm_tf32<0, true, false, false><<<gS, blk, SMEM_BYTES>>>(
        dQ, dK, nullptr, dP, 1024, 1024, 1024, 2048,
        2048LL * 1024, 2048LL * 1024, 2048LL * 2048, 0.03125f);

    softmax_causal<<<dim3(2048, 4), blk>>>(dP, 2048);

    // attn = P @ Vt^T with causal K-trim (output rounded)
    dim3 gA(1024 / BN, 2048 / BM, 4);
    gemm_tf32<0, false, true, true><<<gA, blk, SMEM_BYTES>>>(
        dP, dVt, nullptr, dA, 2048, 2048, 8192, 1024,
        2048LL * 2048, 2048LL, 2048LL * 1024, 1.f);

    // O projection (output rounded, feeds FFN)
    gemm_tf32<1, false, false, true><<<gProj, blk, SMEM_BYTES>>>(
        dA, dWor, bo, dO, 1024, 1024, 1024, 1024, 0, 0, 0, 1.f);

    // FFN + exact GELU -> d_out (NOT rounded)
    dim3 gF(4096 / BN, 8192 / BM, 1);
    gemm_tf32<2, false, false, false><<<gF, blk, SMEM_BYTES>>>(
        dO, dWfr, bff, out, 1024, 1024, 1024, 4096, 0, 0, 0, 1.f);
}

// round 12
// speedup vs baseline: 2.6214x; 1.0396x over previous
#include <cuda_runtime.h>
#include <cmath>
#include <cstdint>

// ---------------------------------------------------------------------------
// DecoderBlock, sm_103 family: tf32 mma.sync.m16n8k8, cp.async 3-stage ring,
// ONE barrier per 32-k stage. Operands pre-rounded to tf32 in gmem.
// smem per stage: A[128x128B] + B[128x128B]; elem (r,k) at byte
//   r*128 + ((k>>2)^(r&7))*16 + (k&3)*4   (conflict-free LDS + cp.async 16B).
// Q/K/V projections fused in one launch (z selects); 1/32 folded into Q (2^-5,
// bit-exact). V stored transposed so P@V is the same NT GEMM with K-trim.
// ---------------------------------------------------------------------------

#define BM 128
#define BN 128
#define BKT 32
#define NTHREADS 256
#define STAGE_BYTES 32768
#define SMEM_BYTES (3 * STAGE_BYTES)

__device__ float g_Q[8192 * 1024];
__device__ float g_K[8192 * 1024];
__device__ float g_Vt[1024 * 8192];
__device__ float g_P[4 * 2048 * 2048];
__device__ float g_Attn[8192 * 1024];
__device__ float g_O[8192 * 1024];
__device__ float g_Xr[8192 * 1024];
__device__ float g_Wr[8 * 1024 * 1024];

__device__ __forceinline__ float f2tf32(float x) {
    unsigned u;
    asm("cvt.rna.tf32.f32 %0, %1;" : "=r"(u) : "f"(x));
    return __uint_as_float(u);
}

__device__ __forceinline__ uint32_t s2u(const void* p) {
    uint32_t a;
    asm("{ .reg .u64 t; cvta.to.shared.u64 t, %1; cvt.u32.u64 %0, t; }"
        : "=r"(a) : "l"(p));
    return a;
}

__device__ __forceinline__ void mma8(float* c, const unsigned* a, const unsigned* b) {
    asm volatile(
        "mma.sync.aligned.m16n8k8.row.col.f32.tf32.tf32.f32 "
        "{%0,%1,%2,%3}, {%4,%5,%6,%7}, {%8,%9}, {%0,%1,%2,%3};\n"
        : "+f"(c[0]), "+f"(c[1]), "+f"(c[2]), "+f"(c[3])
        : "r"(a[0]), "r"(a[1]), "r"(a[2]), "r"(a[3]), "r"(b[0]), "r"(b[1]));
}

#define CP16(dst, src) \
    asm volatile("cp.async.cg.shared.global [%0], [%1], 16;" :: "r"(dst), "l"(src))
#define CP_COMMIT() asm volatile("cp.async.commit_group;")
#define CP_WAIT1() asm volatile("cp.async.wait_group 1;")
#define CP_WAIT0() asm volatile("cp.async.wait_group 0;")

__device__ __forceinline__ float gelu_exact(float v) {
    return 0.5f * v * (1.0f + erff(v * 0.70710678118654752f));
}

// ---- shared mainloop (acc accumulated in caller's registers) ---------------
// Requires: Arow/Brow point at tile row 0; nT stages of 32 k.
struct FragCtx {
    int wm, wn4, g, tig;
};

template <bool PRED>
__device__ __forceinline__ void mainloop(
    const float* __restrict__ Arow, const float* __restrict__ Brow,
    int lda, int ldb, int nT, char* smem, uint32_t sbase,
    const FragCtx& fc, float acc[4][4][4])
{
    const int tid = threadIdx.x;
    auto issue = [&](int t) {
        const int s = t % 3;
        const int k0 = t * BKT;
        const uint32_t dA = sbase + s * STAGE_BYTES;
        const uint32_t dB = dA + 16384;
#pragma unroll
        for (int i = 0; i < 4; i++) {
            const int gi = i * 256 + tid;
            const int r = gi >> 3, j = gi & 7;
            const uint32_t off = r * 128 + ((j ^ (r & 7)) << 4);
            CP16(dA + off, Arow + (size_t)r * lda + k0 + j * 4);
            CP16(dB + off, Brow + (size_t)r * ldb + k0 + j * 4);
        }
        CP_COMMIT();
    };

    issue(0);
    if (nT > 1) issue(1);

    for (int t = 0; t < nT; ++t) {
        if (t < nT - 1) CP_WAIT1(); else CP_WAIT0();
        __syncthreads();           // single barrier per stage (ring-safe)
        if (t + 2 < nT) issue(t + 2);

        const float* a_s = (const float*)(smem + (t % 3) * STAGE_BYTES);
        const float* b_s = a_s + 4096;
#pragma unroll
        for (int kk = 0; kk < BKT; kk += 8) {
            const int j0 = kk >> 2;
            const int sw0 = ((j0 ^ fc.g) << 2) + fc.tig;
            const int sw1 = sw0 ^ 4;
            unsigned af[4][4], bfr[4][2];
#pragma unroll
            for (int im = 0; im < 4; im++) {
                const int m0 = fc.wm * 64 + im * 16 + fc.g;
                af[im][0] = __float_as_uint(a_s[m0 * 32 + sw0]);
                af[im][1] = __float_as_uint(a_s[(m0 + 8) * 32 + sw0]);
                af[im][2] = __float_as_uint(a_s[m0 * 32 + sw1]);
                af[im][3] = __float_as_uint(a_s[(m0 + 8) * 32 + sw1]);
            }
#pragma unroll
            for (int in = 0; in < 4; in++) {
                const int n0 = fc.wn4 * 32 + in * 8 + fc.g;
                bfr[in][0] = __float_as_uint(b_s[n0 * 32 + sw0]);
                bfr[in][1] = __float_as_uint(b_s[n0 * 32 + sw1]);
            }
#pragma unroll
            for (int im = 0; im < 4; im++)
#pragma unroll
                for (int in = 0; in < 4; in++)
                    mma8(acc[im][in], af[im], bfr[in]);
        }
        // no trailing barrier: next iteration's top barrier protects slot reuse
    }
}

// ---- generic GEMM ----------------------------------------------------------
// EPI: 0 = alpha*acc ; 1 = (acc+bias)*alpha ; 2 = gelu(acc+bias) ;
//      3 = transposed (acc+bias)
template <int EPI, bool CAUSAL, bool LIMITK, bool RND>
__global__ void __launch_bounds__(NTHREADS, 2) gemm_tf32(
    const float* __restrict__ A, const float* __restrict__ B,
    const float* __restrict__ bias, float* __restrict__ C,
    int K, int lda, int ldb, int ldc,
    long long strA, long long strB, long long strC, float alpha)
{
    extern __shared__ char smem[];
    const uint32_t sbase = s2u(smem);

    const int bm = blockIdx.y, bn = blockIdx.x;
    if (CAUSAL && bn * BN > bm * BM + (BM - 1)) return;
    A += (long long)blockIdx.z * strA;
    B += (long long)blockIdx.z * strB;
    C += (long long)blockIdx.z * strC;
    const int nT = LIMITK ? (bm + 1) * (128 / BKT) : (K / BKT);

    const int tid = threadIdx.x;
    const int warp = tid >> 5, lane = tid & 31;
    FragCtx fc;
    fc.wm = warp & 1; fc.wn4 = (warp >> 1) & 3;
    fc.g = lane >> 2; fc.tig = lane & 3;

    float acc[4][4][4];
#pragma unroll
    for (int i = 0; i < 4; i++)
#pragma unroll
        for (int j = 0; j < 4; j++)
#pragma unroll
            for (int k = 0; k < 4; k++) acc[i][j][k] = 0.f;

    mainloop<false>(A + (size_t)(bm * BM) * lda, B + (size_t)(bn * BN) * ldb,
                    lda, ldb, nT, smem, sbase, fc, acc);

#pragma unroll
    for (int im = 0; im < 4; im++) {
        const int r0 = bm * BM + fc.wm * 64 + im * 16 + fc.g;
#pragma unroll
        for (int in = 0; in < 4; in++) {
            const int c0 = bn * BN + fc.wn4 * 32 + in * 8 + fc.tig * 2;
            float v00 = acc[im][in][0], v01 = acc[im][in][1];
            float v10 = acc[im][in][2], v11 = acc[im][in][3];
            if (EPI == 0) {
                v00 *= alpha; v01 *= alpha; v10 *= alpha; v11 *= alpha;
            } else {
                const float b0 = bias[c0], b1 = bias[c0 + 1];
                v00 += b0; v01 += b1; v10 += b0; v11 += b1;
                if (EPI == 1) {
                    v00 *= alpha; v01 *= alpha; v10 *= alpha; v11 *= alpha;
                }
                if (EPI == 2) {
                    v00 = gelu_exact(v00); v01 = gelu_exact(v01);
                    v10 = gelu_exact(v10); v11 = gelu_exact(v11);
                }
            }
            if (RND) {
                v00 = f2tf32(v00); v01 = f2tf32(v01);
                v10 = f2tf32(v10); v11 = f2tf32(v11);
            }
            if (EPI == 3) {
                C[(size_t)c0 * ldc + r0] = v00;
                C[(size_t)(c0 + 1) * ldc + r0] = v01;
                C[(size_t)c0 * ldc + r0 + 8] = v10;
                C[(size_t)(c0 + 1) * ldc + r0 + 8] = v11;
            } else {
                *(float2*)(C + (size_t)r0 * ldc + c0) = make_float2(v00, v01);
                *(float2*)(C + (size_t)(r0 + 8) * ldc + c0) = make_float2(v10, v11);
            }
        }
    }
}

// ---- fused Q/K/V projection (z = 0:Q scaled 2^-5, 1:K, 2:V transposed) -----
__global__ void __launch_bounds__(NTHREADS, 2) gemm_qkv(
    const float* __restrict__ X,
    const float* __restrict__ Wq, const float* __restrict__ Wk,
    const float* __restrict__ Wv,
    const float* __restrict__ bq, const float* __restrict__ bk,
    const float* __restrict__ bv,
    float* __restrict__ Q, float* __restrict__ Ko, float* __restrict__ Vt)
{
    extern __shared__ char smem[];
    const uint32_t sbase = s2u(smem);

    const int bm = blockIdx.y, bn = blockIdx.x, z = blockIdx.z;
    const float* W = (z == 0) ? Wq : (z == 1 ? Wk : Wv);
    const float* bias = (z == 0) ? bq : (z == 1 ? bk : bv);
    const float alpha = (z == 0) ? 0.03125f : 1.0f;

    const int tid = threadIdx.x;
    const int warp = tid >> 5, lane = tid & 31;
    FragCtx fc;
    fc.wm = warp & 1; fc.wn4 = (warp >> 1) & 3;
    fc.g = lane >> 2; fc.tig = lane & 3;

    float acc[4][4][4];
#pragma unroll
    for (int i = 0; i < 4; i++)
#pragma unroll
        for (int j = 0; j < 4; j++)
#pragma unroll
            for (int k = 0; k < 4; k++) acc[i][j][k] = 0.f;

    mainloop<false>(X + (size_t)(bm * BM) * 1024, W + (size_t)(bn * BN) * 1024,
                    1024, 1024, 1024 / BKT, smem, sbase, fc, acc);

#pragma unroll
    for (int im = 0; im < 4; im++) {
        const int r0 = bm * BM + fc.wm * 64 + im * 16 + fc.g;
#pragma unroll
        for (int in = 0; in < 4; in++) {
            const int c0 = bn * BN + fc.wn4 * 32 + in * 8 + fc.tig * 2;
            const float b0 = bias[c0], b1 = bias[c0 + 1];
            float v00 = f2tf32((acc[im][in][0] + b0) * alpha);
            float v01 = f2tf32((acc[im][in][1] + b1) * alpha);
            float v10 = f2tf32((acc[im][in][2] + b0) * alpha);
            float v11 = f2tf32((acc[im][in][3] + b1) * alpha);
            if (z == 2) {
                Vt[(size_t)c0 * 8192 + r0] = v00;
                Vt[(size_t)(c0 + 1) * 8192 + r0] = v01;
                Vt[(size_t)c0 * 8192 + r0 + 8] = v10;
                Vt[(size_t)(c0 + 1) * 8192 + r0 + 8] = v11;
            } else {
                float* C = (z == 0) ? Q : Ko;
                *(float2*)(C + (size_t)r0 * 1024 + c0) = make_float2(v00, v01);
                *(float2*)(C + (size_t)(r0 + 8) * 1024 + c0) = make_float2(v10, v11);
            }
        }
    }
}

// ---- helpers ---------------------------------------------------------------
__global__ void round_copy(const float* __restrict__ in, float* __restrict__ out,
                           long long n4) {
    long long i = (long long)blockIdx.x * blockDim.x + threadIdx.x;
    long long stride = (long long)gridDim.x * blockDim.x;
    for (; i < n4; i += stride) {
        float4 v = ((const float4*)in)[i];
        v.x = f2tf32(v.x); v.y = f2tf32(v.y); v.z = f2tf32(v.z); v.w = f2tf32(v.w);
        ((float4*)out)[i] = v;
    }
}

__global__ void softmax_causal(float* __restrict__ P, int len) {
    __shared__ float buf[2048];
    __shared__ float red[33];
    const int q = blockIdx.x, b = blockIdx.y;
    float* row = P + ((size_t)b * len + q) * (size_t)len;
    const int n = q + 1;
    const int tid = threadIdx.x;

    float m = -3.4e38f;
    for (int i = tid; i < n; i += NTHREADS) { float v = row[i]; buf[i] = v; m = fmaxf(m, v); }
#pragma unroll
    for (int o = 16; o; o >>= 1) m = fmaxf(m, __shfl_xor_sync(0xffffffff, m, o));
    if ((tid & 31) == 0) red[tid >> 5] = m;
    __syncthreads();
    if (tid == 0) {
        float v = -3.4e38f;
        for (int i = 0; i < NTHREADS / 32; i++) v = fmaxf(v, red[i]);
        red[32] = v;
    }
    __syncthreads();
    m = red[32];

    float s = 0.f;
    for (int i = tid; i < n; i += NTHREADS) { float e = __expf(buf[i] - m); buf[i] = e; s += e; }
#pragma unroll
    for (int o = 16; o; o >>= 1) s += __shfl_xor_sync(0xffffffff, s, o);
    if ((tid & 31) == 0) red[tid >> 5] = s;
    __syncthreads();
    if (tid == 0) {
        float v = 0.f;
        for (int i = 0; i < NTHREADS / 32; i++) v += red[i];
        red[32] = 1.0f / v;
    }
    __syncthreads();
    const float inv = red[32];

    for (int i = tid; i < n; i += NTHREADS) row[i] = f2tf32(buf[i] * inv);
    const int zend = min(len, ((q >> 7) + 1) << 7);
    for (int i = n + tid; i < zend; i += NTHREADS) row[i] = 0.f;
}

extern "C" void kernel_launch(void* const* d_in, const int* in_sizes, int n_in,
                              void* d_out, int out_size)
{
    const float* x  = (const float*)d_in[0];
    const float* Wq = (const float*)d_in[1];
    const float* bq = (const float*)d_in[2];
    const float* Wk = (const float*)d_in[3];
    const float* bk = (const float*)d_in[4];
    const float* Wv = (const float*)d_in[5];
    const float* bv = (const float*)d_in[6];
    const float* Wo = (const float*)d_in[7];
    const float* bo = (const float*)d_in[8];
    const float* Wf = (const float*)d_in[9];
    const float* bff = (const float*)d_in[10];
    float* out = (float*)d_out;

    float *dQ, *dK, *dVt, *dP, *dA, *dO, *dXr, *dWr;
    cudaGetSymbolAddress((void**)&dQ, g_Q);
    cudaGetSymbolAddress((void**)&dK, g_K);
    cudaGetSymbolAddress((void**)&dVt, g_Vt);
    cudaGetSymbolAddress((void**)&dP, g_P);
    cudaGetSymbolAddress((void**)&dA, g_Attn);
    cudaGetSymbolAddress((void**)&dO, g_O);
    cudaGetSymbolAddress((void**)&dXr, g_Xr);
    cudaGetSymbolAddress((void**)&dWr, g_Wr);
    float* dWqr = dWr;
    float* dWkr = dWr + 1024 * 1024;
    float* dWvr = dWr + 2 * 1024 * 1024;
    float* dWor = dWr + 3 * 1024 * 1024;
    float* dWfr = dWr + 4 * 1024 * 1024;

    cudaFuncSetAttribute(gemm_qkv,
                         cudaFuncAttributeMaxDynamicSharedMemorySize, SMEM_BYTES);
    cudaFuncSetAttribute(gemm_tf32<0, true, false, false>,
                         cudaFuncAttributeMaxDynamicSharedMemorySize, SMEM_BYTES);
    cudaFuncSetAttribute(gemm_tf32<0, false, true, true>,
                         cudaFuncAttributeMaxDynamicSharedMemorySize, SMEM_BYTES);
    cudaFuncSetAttribute(gemm_tf32<1, false, false, true>,
                         cudaFuncAttributeMaxDynamicSharedMemorySize, SMEM_BYTES);
    cudaFuncSetAttribute(gemm_tf32<2, false, false, false>,
                         cudaFuncAttributeMaxDynamicSharedMemorySize, SMEM_BYTES);

    dim3 blk(NTHREADS);

    // pre-round x and weights to tf32
    round_copy<<<256, 256>>>(x, dXr, 8192LL * 1024 / 4);
    round_copy<<<64, 256>>>(Wq, dWqr, 1024LL * 1024 / 4);
    round_copy<<<64, 256>>>(Wk, dWkr, 1024LL * 1024 / 4);
    round_copy<<<64, 256>>>(Wv, dWvr, 1024LL * 1024 / 4);
    round_copy<<<64, 256>>>(Wo, dWor, 1024LL * 1024 / 4);
    round_copy<<<128, 256>>>(Wf, dWfr, 4096LL * 1024 / 4);

    // fused Q/K/V projections (Q pre-scaled by 2^-5; V transposed)
    gemm_qkv<<<dim3(8, 64, 3), blk, SMEM_BYTES>>>(
        dXr, dWqr, dWkr, dWvr, bq, bk, bv, dQ, dK, dVt);

    // scores = Qs K^T (already scaled), causal tile skip
    dim3 gS(16, 16, 4);
    gemm_tf32<0, true, false, false><<<gS, blk, SMEM_BYTES>>>(
        dQ, dK, nullptr, dP, 1024, 1024, 1024, 2048,
        2048LL * 1024, 2048LL * 1024, 2048LL * 2048, 1.f);

    softmax_causal<<<dim3(2048, 4), blk>>>(dP, 2048);

    // attn = P @ Vt^T with causal K-trim (rounded output)
    dim3 gA(8, 16, 4);
    gemm_tf32<0, false, true, true><<<gA, blk, SMEM_BYTES>>>(
        dP, dVt, nullptr, dA, 2048, 2048, 8192, 1024,
        2048LL * 2048, 2048LL, 2048LL * 1024, 1.f);

    // O projection (rounded, feeds FFN)
    dim3 gProj(8, 64, 1);
    gemm_tf32<1, false, false, true><<<gProj, blk, SMEM_BYTES>>>(
        dA, dWor, bo, dO, 1024, 1024, 1024, 1024, 0, 0, 0, 1.f);

    // FFN + exact GELU -> d_out
    dim3 gF(32, 64, 1);
    gemm_tf32<2, false, false, false><<<gF, blk, SMEM_BYTES>>>(
        dO, dWfr, bff, out, 1024, 1024, 1024, 4096, 0, 0, 0, 1.f);
}

// round 14
// speedup vs baseline: 2.7510x; 1.0494x over previous
#include <cuda_runtime.h>
#include <cmath>
#include <cstdint>

// ---------------------------------------------------------------------------
// DecoderBlock, sm_103 family: tf32 mma.sync.m16n8k8, cp.async 3-stage ring,
// one barrier per 32-k stage, operands pre-rounded to tf32 in gmem.
// R13: 64x64 warp tiles — CTA 128x128 with 128 threads (2x2 warps).
//   Per kk8: 32 frag LDS + 32 MMA per warp (was 24+16) -> 2.0 slots/MMA.
// smem per stage: A[128x128B] + B[128x128B]; elem (r,k) at byte
//   r*128 + ((k>>2)^(r&7))*16 + (k&3)*4   (conflict-free LDS + cp.async 16B).
// ---------------------------------------------------------------------------

#define BM 128
#define BN 128
#define BKT 32
#define NTHREADS 128
#define STAGE_BYTES 32768
#define SMEM_BYTES (3 * STAGE_BYTES)

__device__ float g_Q[8192 * 1024];
__device__ float g_K[8192 * 1024];
__device__ float g_Vt[1024 * 8192];
__device__ float g_P[4 * 2048 * 2048];
__device__ float g_Attn[8192 * 1024];
__device__ float g_O[8192 * 1024];
__device__ float g_Xr[8192 * 1024];
__device__ float g_Wr[8 * 1024 * 1024];

__device__ __forceinline__ float f2tf32(float x) {
    unsigned u;
    asm("cvt.rna.tf32.f32 %0, %1;" : "=r"(u) : "f"(x));
    return __uint_as_float(u);
}

__device__ __forceinline__ uint32_t s2u(const void* p) {
    uint32_t a;
    asm("{ .reg .u64 t; cvta.to.shared.u64 t, %1; cvt.u32.u64 %0, t; }"
        : "=r"(a) : "l"(p));
    return a;
}

__device__ __forceinline__ void mma8(float* c, const unsigned* a, const unsigned* b) {
    asm volatile(
        "mma.sync.aligned.m16n8k8.row.col.f32.tf32.tf32.f32 "
        "{%0,%1,%2,%3}, {%4,%5,%6,%7}, {%8,%9}, {%0,%1,%2,%3};\n"
        : "+f"(c[0]), "+f"(c[1]), "+f"(c[2]), "+f"(c[3])
        : "r"(a[0]), "r"(a[1]), "r"(a[2]), "r"(a[3]), "r"(b[0]), "r"(b[1]));
}

#define CP16(dst, src) \
    asm volatile("cp.async.cg.shared.global [%0], [%1], 16;" :: "r"(dst), "l"(src))
#define CP_COMMIT() asm volatile("cp.async.commit_group;")
#define CP_WAIT1() asm volatile("cp.async.wait_group 1;")
#define CP_WAIT0() asm volatile("cp.async.wait_group 0;")

__device__ __forceinline__ float gelu_exact(float v) {
    return 0.5f * v * (1.0f + erff(v * 0.70710678118654752f));
}

// ---- shared mainloop: 2x2 warp grid, 64x64 warp tiles ----------------------
struct FragCtx {
    int wm, wn2, g, tig;
};

__device__ __forceinline__ void mainloop(
    const float* __restrict__ Arow, const float* __restrict__ Brow,
    int lda, int ldb, int nT, char* smem, uint32_t sbase,
    const FragCtx& fc, float acc[4][8][4])
{
    const int tid = threadIdx.x;
    auto issue = [&](int t) {
        const int s = t % 3;
        const int k0 = t * BKT;
        const uint32_t dA = sbase + s * STAGE_BYTES;
        const uint32_t dB = dA + 16384;
#pragma unroll
        for (int i = 0; i < 8; i++) {
            const int gi = i * 128 + tid;       // 0..1023
            const int r = gi >> 3, j = gi & 7;
            const uint32_t off = r * 128 + ((j ^ (r & 7)) << 4);
            CP16(dA + off, Arow + (size_t)r * lda + k0 + j * 4);
            CP16(dB + off, Brow + (size_t)r * ldb + k0 + j * 4);
        }
        CP_COMMIT();
    };

    issue(0);
    if (nT > 1) issue(1);

    for (int t = 0; t < nT; ++t) {
        if (t < nT - 1) CP_WAIT1(); else CP_WAIT0();
        __syncthreads();
        if (t + 2 < nT) issue(t + 2);

        const float* a_s = (const float*)(smem + (t % 3) * STAGE_BYTES);
        const float* b_s = a_s + 4096;
#pragma unroll
        for (int kk = 0; kk < BKT; kk += 8) {
            const int j0 = kk >> 2;
            const int sw0 = ((j0 ^ fc.g) << 2) + fc.tig;
            const int sw1 = sw0 ^ 4;
            unsigned af[4][4], bfr[8][2];
#pragma unroll
            for (int im = 0; im < 4; im++) {
                const int m0 = fc.wm * 64 + im * 16 + fc.g;
                af[im][0] = __float_as_uint(a_s[m0 * 32 + sw0]);
                af[im][1] = __float_as_uint(a_s[(m0 + 8) * 32 + sw0]);
                af[im][2] = __float_as_uint(a_s[m0 * 32 + sw1]);
                af[im][3] = __float_as_uint(a_s[(m0 + 8) * 32 + sw1]);
            }
#pragma unroll
            for (int in = 0; in < 8; in++) {
                const int n0 = fc.wn2 * 64 + in * 8 + fc.g;
                bfr[in][0] = __float_as_uint(b_s[n0 * 32 + sw0]);
                bfr[in][1] = __float_as_uint(b_s[n0 * 32 + sw1]);
            }
#pragma unroll
            for (int im = 0; im < 4; im++)
#pragma unroll
                for (int in = 0; in < 8; in++)
                    mma8(acc[im][in], af[im], bfr[in]);
        }
        // no trailing barrier: next top barrier protects ring-slot reuse
    }
}

// ---- generic GEMM ----------------------------------------------------------
// EPI: 0 = alpha*acc ; 1 = (acc+bias)*alpha ; 2 = gelu(acc+bias) ;
//      3 = transposed (acc+bias)
template <int EPI, bool CAUSAL, bool LIMITK, bool RND>
__global__ void __launch_bounds__(NTHREADS, 2) gemm_tf32(
    const float* __restrict__ A, const float* __restrict__ B,
    const float* __restrict__ bias, float* __restrict__ C,
    int K, int lda, int ldb, int ldc,
    long long strA, long long strB, long long strC, float alpha)
{
    extern __shared__ char smem[];
    const uint32_t sbase = s2u(smem);

    const int bm = blockIdx.y, bn = blockIdx.x;
    if (CAUSAL && bn * BN > bm * BM + (BM - 1)) return;
    A += (long long)blockIdx.z * strA;
    B += (long long)blockIdx.z * strB;
    C += (long long)blockIdx.z * strC;
    const int nT = LIMITK ? (bm + 1) * (128 / BKT) : (K / BKT);

    const int tid = threadIdx.x;
    const int warp = tid >> 5, lane = tid & 31;
    FragCtx fc;
    fc.wm = warp & 1; fc.wn2 = warp >> 1;
    fc.g = lane >> 2; fc.tig = lane & 3;

    float acc[4][8][4];
#pragma unroll
    for (int i = 0; i < 4; i++)
#pragma unroll
        for (int j = 0; j < 8; j++)
#pragma unroll
            for (int k = 0; k < 4; k++) acc[i][j][k] = 0.f;

    mainloop(A + (size_t)(bm * BM) * lda, B + (size_t)(bn * BN) * ldb,
             lda, ldb, nT, smem, sbase, fc, acc);

#pragma unroll
    for (int im = 0; im < 4; im++) {
        const int r0 = bm * BM + fc.wm * 64 + im * 16 + fc.g;
#pragma unroll
        for (int in = 0; in < 8; in++) {
            const int c0 = bn * BN + fc.wn2 * 64 + in * 8 + fc.tig * 2;
            float v00 = acc[im][in][0], v01 = acc[im][in][1];
            float v10 = acc[im][in][2], v11 = acc[im][in][3];
            if (EPI == 0) {
                v00 *= alpha; v01 *= alpha; v10 *= alpha; v11 *= alpha;
            } else {
                const float b0 = bias[c0], b1 = bias[c0 + 1];
                v00 += b0; v01 += b1; v10 += b0; v11 += b1;
                if (EPI == 1) {
                    v00 *= alpha; v01 *= alpha; v10 *= alpha; v11 *= alpha;
                }
                if (EPI == 2) {
                    v00 = gelu_exact(v00); v01 = gelu_exact(v01);
                    v10 = gelu_exact(v10); v11 = gelu_exact(v11);
                }
            }
            if (RND) {
                v00 = f2tf32(v00); v01 = f2tf32(v01);
                v10 = f2tf32(v10); v11 = f2tf32(v11);
            }
            if (EPI == 3) {
                C[(size_t)c0 * ldc + r0] = v00;
                C[(size_t)(c0 + 1) * ldc + r0] = v01;
                C[(size_t)c0 * ldc + r0 + 8] = v10;
                C[(size_t)(c0 + 1) * ldc + r0 + 8] = v11;
            } else {
                *(float2*)(C + (size_t)r0 * ldc + c0) = make_float2(v00, v01);
                *(float2*)(C + (size_t)(r0 + 8) * ldc + c0) = make_float2(v10, v11);
            }
        }
    }
}

// ---- fused Q/K/V projection (z = 0:Q scaled 2^-5, 1:K, 2:V transposed) -----
__global__ void __launch_bounds__(NTHREADS, 2) gemm_qkv(
    const float* __restrict__ X,
    const float* __restrict__ Wq, const float* __restrict__ Wk,
    const float* __restrict__ Wv,
    const float* __restrict__ bq, const float* __restrict__ bk,
    const float* __restrict__ bv,
    float* __restrict__ Q, float* __restrict__ Ko, float* __restrict__ Vt)
{
    extern __shared__ char smem[];
    const uint32_t sbase = s2u(smem);

    const int bm = blockIdx.y, bn = blockIdx.x, z = blockIdx.z;
    const float* W = (z == 0) ? Wq : (z == 1 ? Wk : Wv);
    const float* bias = (z == 0) ? bq : (z == 1 ? bk : bv);
    const float alpha = (z == 0) ? 0.03125f : 1.0f;

    const int tid = threadIdx.x;
    const int warp = tid >> 5, lane = tid & 31;
    FragCtx fc;
    fc.wm = warp & 1; fc.wn2 = warp >> 1;
    fc.g = lane >> 2; fc.tig = lane & 3;

    float acc[4][8][4];
#pragma unroll
    for (int i = 0; i < 4; i++)
#pragma unroll
        for (int j = 0; j < 8; j++)
#pragma unroll
            for (int k = 0; k < 4; k++) acc[i][j][k] = 0.f;

    mainloop(X + (size_t)(bm * BM) * 1024, W + (size_t)(bn * BN) * 1024,
             1024, 1024, 1024 / BKT, smem, sbase, fc, acc);

#pragma unroll
    for (int im = 0; im < 4; im++) {
        const int r0 = bm * BM + fc.wm * 64 + im * 16 + fc.g;
#pragma unroll
        for (int in = 0; in < 8; in++) {
            const int c0 = bn * BN + fc.wn2 * 64 + in * 8 + fc.tig * 2;
            const float b0 = bias[c0], b1 = bias[c0 + 1];
            float v00 = f2tf32((acc[im][in][0] + b0) * alpha);
            float v01 = f2tf32((acc[im][in][1] + b1) * alpha);
            float v10 = f2tf32((acc[im][in][2] + b0) * alpha);
            float v11 = f2tf32((acc[im][in][3] + b1) * alpha);
            if (z == 2) {
                Vt[(size_t)c0 * 8192 + r0] = v00;
                Vt[(size_t)(c0 + 1) * 8192 + r0] = v01;
                Vt[(size_t)c0 * 8192 + r0 + 8] = v10;
                Vt[(size_t)(c0 + 1) * 8192 + r0 + 8] = v11;
            } else {
                float* C = (z == 0) ? Q : Ko;
                *(float2*)(C + (size_t)r0 * 1024 + c0) = make_float2(v00, v01);
                *(float2*)(C + (size_t)(r0 + 8) * 1024 + c0) = make_float2(v10, v11);
            }
        }
    }
}

// ---- helpers ---------------------------------------------------------------
__global__ void round_copy(const float* __restrict__ in, float* __restrict__ out,
                           long long n4) {
    long long i = (long long)blockIdx.x * blockDim.x + threadIdx.x;
    long long stride = (long long)gridDim.x * blockDim.x;
    for (; i < n4; i += stride) {
        float4 v = ((const float4*)in)[i];
        v.x = f2tf32(v.x); v.y = f2tf32(v.y); v.z = f2tf32(v.z); v.w = f2tf32(v.w);
        ((float4*)out)[i] = v;
    }
}

__global__ void softmax_causal(float* __restrict__ P, int len) {
    __shared__ float buf[2048];
    __shared__ float red[33];
    const int q = blockIdx.x, b = blockIdx.y;
    float* row = P + ((size_t)b * len + q) * (size_t)len;
    const int n = q + 1;
    const int tid = threadIdx.x;

    float m = -3.4e38f;
    for (int i = tid; i < n; i += 256) { float v = row[i]; buf[i] = v; m = fmaxf(m, v); }
#pragma unroll
    for (int o = 16; o; o >>= 1) m = fmaxf(m, __shfl_xor_sync(0xffffffff, m, o));
    if ((tid & 31) == 0) red[tid >> 5] = m;
    __syncthreads();
    if (tid == 0) {
        float v = -3.4e38f;
        for (int i = 0; i < 8; i++) v = fmaxf(v, red[i]);
        red[32] = v;
    }
    __syncthreads();
    m = red[32];

    float s = 0.f;
    for (int i = tid; i < n; i += 256) { float e = __expf(buf[i] - m); buf[i] = e; s += e; }
#pragma unroll
    for (int o = 16; o; o >>= 1) s += __shfl_xor_sync(0xffffffff, s, o);
    if ((tid & 31) == 0) red[tid >> 5] = s;
    __syncthreads();
    if (tid == 0) {
        float v = 0.f;
        for (int i = 0; i < 8; i++) v += red[i];
        red[32] = 1.0f / v;
    }
    __syncthreads();
    const float inv = red[32];

    for (int i = tid; i < n; i += 256) row[i] = f2tf32(buf[i] * inv);
    const int zend = min(len, ((q >> 7) + 1) << 7);
    for (int i = n + tid; i < zend; i += 256) row[i] = 0.f;
}

extern "C" void kernel_launch(void* const* d_in, const int* in_sizes, int n_in,
                              void* d_out, int out_size)
{
    const float* x  = (const float*)d_in[0];
    const float* Wq = (const float*)d_in[1];
    const float* bq = (const float*)d_in[2];
    const float* Wk = (const float*)d_in[3];
    const float* bk = (const float*)d_in[4];
    const float* Wv = (const float*)d_in[5];
    const float* bv = (const float*)d_in[6];
    const float* Wo = (const float*)d_in[7];
    const float* bo = (const float*)d_in[8];
    const float* Wf = (const float*)d_in[9];
    const float* bff = (const float*)d_in[10];
    float* out = (float*)d_out;

    float *dQ, *dK, *dVt, *dP, *dA, *dO, *dXr, *dWr;
    cudaGetSymbolAddress((void**)&dQ, g_Q);
    cudaGetSymbolAddress((void**)&dK, g_K);
    cudaGetSymbolAddress((void**)&dVt, g_Vt);
    cudaGetSymbolAddress((void**)&dP, g_P);
    cudaGetSymbolAddress((void**)&dA, g_Attn);
    cudaGetSymbolAddress((void**)&dO, g_O);
    cudaGetSymbolAddress((void**)&dXr, g_Xr);
    cudaGetSymbolAddress((void**)&dWr, g_Wr);
    float* dWqr = dWr;
    float* dWkr = dWr + 1024 * 1024;
    float* dWvr = dWr + 2 * 1024 * 1024;
    float* dWor = dWr + 3 * 1024 * 1024;
    float* dWfr = dWr + 4 * 1024 * 1024;

    cudaFuncSetAttribute(gemm_qkv,
                         cudaFuncAttributeMaxDynamicSharedMemorySize, SMEM_BYTES);
    cudaFuncSetAttribute(gemm_tf32<0, true, false, false>,
                         cudaFuncAttributeMaxDynamicSharedMemorySize, SMEM_BYTES);
    cudaFuncSetAttribute(gemm_tf32<0, false, true, true>,
                         cudaFuncAttributeMaxDynamicSharedMemorySize, SMEM_BYTES);
    cudaFuncSetAttribute(gemm_tf32<1, false, false, true>,
                         cudaFuncAttributeMaxDynamicSharedMemorySize, SMEM_BYTES);
    cudaFuncSetAttribute(gemm_tf32<2, false, false, false>,
                         cudaFuncAttributeMaxDynamicSharedMemorySize, SMEM_BYTES);

    dim3 blk(NTHREADS);
    dim3 blk256(256);

    // pre-round x and weights to tf32
    round_copy<<<256, 256>>>(x, dXr, 8192LL * 1024 / 4);
    round_copy<<<64, 256>>>(Wq, dWqr, 1024LL * 1024 / 4);
    round_copy<<<64, 256>>>(Wk, dWkr, 1024LL * 1024 / 4);
    round_copy<<<64, 256>>>(Wv, dWvr, 1024LL * 1024 / 4);
    round_copy<<<64, 256>>>(Wo, dWor, 1024LL * 1024 / 4);
    round_copy<<<128, 256>>>(Wf, dWfr, 4096LL * 1024 / 4);

    // fused Q/K/V projections (Q pre-scaled by 2^-5; V transposed)
    gemm_qkv<<<dim3(8, 64, 3), blk, SMEM_BYTES>>>(
        dXr, dWqr, dWkr, dWvr, bq, bk, bv, dQ, dK, dVt);

    // scores = Qs K^T (already scaled), causal tile skip
    dim3 gS(16, 16, 4);
    gemm_tf32<0, true, false, false><<<gS, blk, SMEM_BYTES>>>(
        dQ, dK, nullptr, dP, 1024, 1024, 1024, 2048,
        2048LL * 1024, 2048LL * 1024, 2048LL * 2048, 1.f);

    softmax_causal<<<dim3(2048, 4), blk256>>>(dP, 2048);

    // attn = P @ Vt^T with causal K-trim (rounded output)
    dim3 gA(8, 16, 4);
    gemm_tf32<0, false, true, true><<<gA, blk, SMEM_BYTES>>>(
        dP, dVt, nullptr, dA, 2048, 2048, 8192, 1024,
        2048LL * 2048, 2048LL, 2048LL * 1024, 1.f);

    // O projection (rounded, feeds FFN)
    dim3 gProj(8, 64, 1);
    gemm_tf32<1, false, false, true><<<gProj, blk, SMEM_BYTES>>>(
        dA, dWor, bo, dO, 1024, 1024, 1024, 1024, 0, 0, 0, 1.f);

    // FFN + exact GELU -> d_out
    dim3 gF(32, 64, 1);
    gemm_tf32<2, false, false, false><<<gF, blk, SMEM_BYTES>>>(
        dO, dWfr, bff, out, 1024, 1024, 1024, 4096, 0, 0, 0, 1.f);
}

// round 15
// speedup vs baseline: 2.7808x; 1.0109x over previous
#include <cuda_runtime.h>
#include <cmath>
#include <cstdint>

// ---------------------------------------------------------------------------
// DecoderBlock, sm_103 family: tf32 mma.sync.m16n8k8, cp.async 3-stage ring,
// one barrier per 32-k stage, operands pre-rounded to tf32 in gmem.
// R15: fragment double-buffering (LDS latency hidden behind MMA pipe),
//      LPT dispatch for LIMITK (heavy bm first), merged rounding pre-pass.
// 64x64 warp tiles; CTA 128x128, 128 threads (2x2 warps).
// smem per stage: A[128x128B]+B[128x128B]; elem (r,k) at byte
//   r*128 + ((k>>2)^(r&7))*16 + (k&3)*4   (conflict-free LDS + cp.async 16B).
// ---------------------------------------------------------------------------

#define BM 128
#define BN 128
#define BKT 32
#define NTHREADS 128
#define STAGE_BYTES 32768
#define SMEM_BYTES (3 * STAGE_BYTES)

__device__ float g_Q[8192 * 1024];
__device__ float g_K[8192 * 1024];
__device__ float g_Vt[1024 * 8192];
__device__ float g_P[4 * 2048 * 2048];
__device__ float g_Attn[8192 * 1024];
__device__ float g_O[8192 * 1024];
__device__ float g_Xr[8192 * 1024];
__device__ float g_Wr[8 * 1024 * 1024];

__device__ __forceinline__ float f2tf32(float x) {
    unsigned u;
    asm("cvt.rna.tf32.f32 %0, %1;" : "=r"(u) : "f"(x));
    return __uint_as_float(u);
}

__device__ __forceinline__ uint32_t s2u(const void* p) {
    uint32_t a;
    asm("{ .reg .u64 t; cvta.to.shared.u64 t, %1; cvt.u32.u64 %0, t; }"
        : "=r"(a) : "l"(p));
    return a;
}

__device__ __forceinline__ void mma8(float* c, const unsigned* a, const unsigned* b) {
    asm volatile(
        "mma.sync.aligned.m16n8k8.row.col.f32.tf32.tf32.f32 "
        "{%0,%1,%2,%3}, {%4,%5,%6,%7}, {%8,%9}, {%0,%1,%2,%3};\n"
        : "+f"(c[0]), "+f"(c[1]), "+f"(c[2]), "+f"(c[3])
        : "r"(a[0]), "r"(a[1]), "r"(a[2]), "r"(a[3]), "r"(b[0]), "r"(b[1]));
}

#define CP16(dst, src) \
    asm volatile("cp.async.cg.shared.global [%0], [%1], 16;" :: "r"(dst), "l"(src))
#define CP_COMMIT() asm volatile("cp.async.commit_group;")
#define CP_WAIT1() asm volatile("cp.async.wait_group 1;")
#define CP_WAIT0() asm volatile("cp.async.wait_group 0;")

__device__ __forceinline__ float gelu_exact(float v) {
    return 0.5f * v * (1.0f + erff(v * 0.70710678118654752f));
}

// ---- shared mainloop: 2x2 warp grid, 64x64 warp tiles, frag double-buffer --
struct FragCtx {
    int wm, wn2, g, tig;
};

__device__ __forceinline__ void ld_frags(
    const float* __restrict__ a_s, const float* __restrict__ b_s,
    int kk, const FragCtx& fc, unsigned af[4][4], unsigned bfr[8][2])
{
    const int j0 = kk >> 2;
    const int sw0 = ((j0 ^ fc.g) << 2) + fc.tig;
    const int sw1 = sw0 ^ 4;
#pragma unroll
    for (int im = 0; im < 4; im++) {
        const int m0 = fc.wm * 64 + im * 16 + fc.g;
        af[im][0] = __float_as_uint(a_s[m0 * 32 + sw0]);
        af[im][1] = __float_as_uint(a_s[(m0 + 8) * 32 + sw0]);
        af[im][2] = __float_as_uint(a_s[m0 * 32 + sw1]);
        af[im][3] = __float_as_uint(a_s[(m0 + 8) * 32 + sw1]);
    }
#pragma unroll
    for (int in = 0; in < 8; in++) {
        const int n0 = fc.wn2 * 64 + in * 8 + fc.g;
        bfr[in][0] = __float_as_uint(b_s[n0 * 32 + sw0]);
        bfr[in][1] = __float_as_uint(b_s[n0 * 32 + sw1]);
    }
}

__device__ __forceinline__ void mainloop(
    const float* __restrict__ Arow, const float* __restrict__ Brow,
    int lda, int ldb, int nT, char* smem, uint32_t sbase,
    const FragCtx& fc, float acc[4][8][4])
{
    const int tid = threadIdx.x;
    auto issue = [&](int t) {
        const int s = t % 3;
        const int k0 = t * BKT;
        const uint32_t dA = sbase + s * STAGE_BYTES;
        const uint32_t dB = dA + 16384;
#pragma unroll
        for (int i = 0; i < 8; i++) {
            const int gi = i * 128 + tid;       // 0..1023
            const int r = gi >> 3, j = gi & 7;
            const uint32_t off = r * 128 + ((j ^ (r & 7)) << 4);
            CP16(dA + off, Arow + (size_t)r * lda + k0 + j * 4);
            CP16(dB + off, Brow + (size_t)r * ldb + k0 + j * 4);
        }
        CP_COMMIT();
    };

    issue(0);
    if (nT > 1) issue(1);

    unsigned af[2][4][4], bfr[2][8][2];

    for (int t = 0; t < nT; ++t) {
        if (t < nT - 1) CP_WAIT1(); else CP_WAIT0();
        __syncthreads();
        if (t + 2 < nT) issue(t + 2);

        const float* a_s = (const float*)(smem + (t % 3) * STAGE_BYTES);
        const float* b_s = a_s + 4096;

        ld_frags(a_s, b_s, 0, fc, af[0], bfr[0]);
#pragma unroll
        for (int kk = 0; kk < BKT; kk += 8) {
            const int cur = (kk >> 3) & 1;
            if (kk + 8 < BKT)
                ld_frags(a_s, b_s, kk + 8, fc, af[cur ^ 1], bfr[cur ^ 1]);
#pragma unroll
            for (int im = 0; im < 4; im++)
#pragma unroll
                for (int in = 0; in < 8; in++)
                    mma8(acc[im][in], af[cur][im], bfr[cur][in]);
        }
        // no trailing barrier: next top barrier protects ring-slot reuse
    }
}

// ---- generic GEMM ----------------------------------------------------------
// EPI: 0 = alpha*acc ; 1 = (acc+bias)*alpha ; 2 = gelu(acc+bias) ;
//      3 = transposed (acc+bias)
// LIMITK also reverses bm (LPT: heavy tiles dispatched first).
template <int EPI, bool CAUSAL, bool LIMITK, bool RND>
__global__ void __launch_bounds__(NTHREADS, 2) gemm_tf32(
    const float* __restrict__ A, const float* __restrict__ B,
    const float* __restrict__ bias, float* __restrict__ C,
    int K, int lda, int ldb, int ldc,
    long long strA, long long strB, long long strC, float alpha)
{
    extern __shared__ char smem[];
    const uint32_t sbase = s2u(smem);

    const int bm = LIMITK ? (gridDim.y - 1 - blockIdx.y) : blockIdx.y;
    const int bn = blockIdx.x;
    if (CAUSAL && bn * BN > bm * BM + (BM - 1)) return;
    A += (long long)blockIdx.z * strA;
    B += (long long)blockIdx.z * strB;
    C += (long long)blockIdx.z * strC;
    const int nT = LIMITK ? (bm + 1) * (128 / BKT) : (K / BKT);

    const int tid = threadIdx.x;
    const int warp = tid >> 5, lane = tid & 31;
    FragCtx fc;
    fc.wm = warp & 1; fc.wn2 = warp >> 1;
    fc.g = lane >> 2; fc.tig = lane & 3;

    float acc[4][8][4];
#pragma unroll
    for (int i = 0; i < 4; i++)
#pragma unroll
        for (int j = 0; j < 8; j++)
#pragma unroll
            for (int k = 0; k < 4; k++) acc[i][j][k] = 0.f;

    mainloop(A + (size_t)(bm * BM) * lda, B + (size_t)(bn * BN) * ldb,
             lda, ldb, nT, smem, sbase, fc, acc);

#pragma unroll
    for (int im = 0; im < 4; im++) {
        const int r0 = bm * BM + fc.wm * 64 + im * 16 + fc.g;
#pragma unroll
        for (int in = 0; in < 8; in++) {
            const int c0 = bn * BN + fc.wn2 * 64 + in * 8 + fc.tig * 2;
            float v00 = acc[im][in][0], v01 = acc[im][in][1];
            float v10 = acc[im][in][2], v11 = acc[im][in][3];
            if (EPI == 0) {
                v00 *= alpha; v01 *= alpha; v10 *= alpha; v11 *= alpha;
            } else {
                const float b0 = bias[c0], b1 = bias[c0 + 1];
                v00 += b0; v01 += b1; v10 += b0; v11 += b1;
                if (EPI == 1) {
                    v00 *= alpha; v01 *= alpha; v10 *= alpha; v11 *= alpha;
                }
                if (EPI == 2) {
                    v00 = gelu_exact(v00); v01 = gelu_exact(v01);
                    v10 = gelu_exact(v10); v11 = gelu_exact(v11);
                }
            }
            if (RND) {
                v00 = f2tf32(v00); v01 = f2tf32(v01);
                v10 = f2tf32(v10); v11 = f2tf32(v11);
            }
            if (EPI == 3) {
                C[(size_t)c0 * ldc + r0] = v00;
                C[(size_t)(c0 + 1) * ldc + r0] = v01;
                C[(size_t)c0 * ldc + r0 + 8] = v10;
                C[(size_t)(c0 + 1) * ldc + r0 + 8] = v11;
            } else {
                *(float2*)(C + (size_t)r0 * ldc + c0) = make_float2(v00, v01);
                *(float2*)(C + (size_t)(r0 + 8) * ldc + c0) = make_float2(v10, v11);
            }
        }
    }
}

// ---- fused Q/K/V projection (z = 0:Q scaled 2^-5, 1:K, 2:V transposed) -----
__global__ void __launch_bounds__(NTHREADS, 2) gemm_qkv(
    const float* __restrict__ X,
    const float* __restrict__ Wq, const float* __restrict__ Wk,
    const float* __restrict__ Wv,
    const float* __restrict__ bq, const float* __restrict__ bk,
    const float* __restrict__ bv,
    float* __restrict__ Q, float* __restrict__ Ko, float* __restrict__ Vt)
{
    extern __shared__ char smem[];
    const uint32_t sbase = s2u(smem);

    const int bm = blockIdx.y, bn = blockIdx.x, z = blockIdx.z;
    const float* W = (z == 0) ? Wq : (z == 1 ? Wk : Wv);
    const float* bias = (z == 0) ? bq : (z == 1 ? bk : bv);
    const float alpha = (z == 0) ? 0.03125f : 1.0f;

    const int tid = threadIdx.x;
    const int warp = tid >> 5, lane = tid & 31;
    FragCtx fc;
    fc.wm = warp & 1; fc.wn2 = warp >> 1;
    fc.g = lane >> 2; fc.tig = lane & 3;

    float acc[4][8][4];
#pragma unroll
    for (int i = 0; i < 4; i++)
#pragma unroll
        for (int j = 0; j < 8; j++)
#pragma unroll
            for (int k = 0; k < 4; k++) acc[i][j][k] = 0.f;

    mainloop(X + (size_t)(bm * BM) * 1024, W + (size_t)(bn * BN) * 1024,
             1024, 1024, 1024 / BKT, smem, sbase, fc, acc);

#pragma unroll
    for (int im = 0; im < 4; im++) {
        const int r0 = bm * BM + fc.wm * 64 + im * 16 + fc.g;
#pragma unroll
        for (int in = 0; in < 8; in++) {
            const int c0 = bn * BN + fc.wn2 * 64 + in * 8 + fc.tig * 2;
            const float b0 = bias[c0], b1 = bias[c0 + 1];
            float v00 = f2tf32((acc[im][in][0] + b0) * alpha);
            float v01 = f2tf32((acc[im][in][1] + b1) * alpha);
            float v10 = f2tf32((acc[im][in][2] + b0) * alpha);
            float v11 = f2tf32((acc[im][in][3] + b1) * alpha);
            if (z == 2) {
                Vt[(size_t)c0 * 8192 + r0] = v00;
                Vt[(size_t)(c0 + 1) * 8192 + r0] = v01;
                Vt[(size_t)c0 * 8192 + r0 + 8] = v10;
                Vt[(size_t)(c0 + 1) * 8192 + r0 + 8] = v11;
            } else {
                float* C = (z == 0) ? Q : Ko;
                *(float2*)(C + (size_t)r0 * 1024 + c0) = make_float2(v00, v01);
                *(float2*)(C + (size_t)(r0 + 8) * 1024 + c0) = make_float2(v10, v11);
            }
        }
    }
}

// ---- merged tf32 rounding pre-pass (one launch, blockIdx.y = segment) ------
__global__ void round_all(
    const float* __restrict__ x,  float* __restrict__ xo,
    const float* __restrict__ w0, float* __restrict__ o0,
    const float* __restrict__ w1, float* __restrict__ o1,
    const float* __restrict__ w2, float* __restrict__ o2,
    const float* __restrict__ w3, float* __restrict__ o3,
    const float* __restrict__ w4, float* __restrict__ o4)
{
    const int seg = blockIdx.y;
    const float* in;
    float* out;
    long long n4;
    if (seg == 0)      { in = x;  out = xo; n4 = 8192LL * 1024 / 4; }
    else if (seg == 1) { in = w0; out = o0; n4 = 1024LL * 1024 / 4; }
    else if (seg == 2) { in = w1; out = o1; n4 = 1024LL * 1024 / 4; }
    else if (seg == 3) { in = w2; out = o2; n4 = 1024LL * 1024 / 4; }
    else if (seg == 4) { in = w3; out = o3; n4 = 1024LL * 1024 / 4; }
    else               { in = w4; out = o4; n4 = 4096LL * 1024 / 4; }

    long long i = (long long)blockIdx.x * blockDim.x + threadIdx.x;
    long long stride = (long long)gridDim.x * blockDim.x;
    for (; i < n4; i += stride) {
        float4 v = ((const float4*)in)[i];
        v.x = f2tf32(v.x); v.y = f2tf32(v.y); v.z = f2tf32(v.z); v.w = f2tf32(v.w);
        ((float4*)out)[i] = v;
    }
}

__global__ void softmax_causal(float* __restrict__ P, int len) {
    __shared__ float buf[2048];
    __shared__ float red[33];
    const int q = blockIdx.x, b = blockIdx.y;
    float* row = P + ((size_t)b * len + q) * (size_t)len;
    const int n = q + 1;
    const int tid = threadIdx.x;

    float m = -3.4e38f;
    for (int i = tid; i < n; i += 256) { float v = row[i]; buf[i] = v; m = fmaxf(m, v); }
#pragma unroll
    for (int o = 16; o; o >>= 1) m = fmaxf(m, __shfl_xor_sync(0xffffffff, m, o));
    if ((tid & 31) == 0) red[tid >> 5] = m;
    __syncthreads();
    if (tid == 0) {
        float v = -3.4e38f;
        for (int i = 0; i < 8; i++) v = fmaxf(v, red[i]);
        red[32] = v;
    }
    __syncthreads();
    m = red[32];

    float s = 0.f;
    for (int i = tid; i < n; i += 256) { float e = __expf(buf[i] - m); buf[i] = e; s += e; }
#pragma unroll
    for (int o = 16; o; o >>= 1) s += __shfl_xor_sync(0xffffffff, s, o);
    if ((tid & 31) == 0) red[tid >> 5] = s;
    __syncthreads();
    if (tid == 0) {
        float v = 0.f;
        for (int i = 0; i < 8; i++) v += red[i];
        red[32] = 1.0f / v;
    }
    __syncthreads();
    const float inv = red[32];

    for (int i = tid; i < n; i += 256) row[i] = f2tf32(buf[i] * inv);
    const int zend = min(len, ((q >> 7) + 1) << 7);
    for (int i = n + tid; i < zend; i += 256) row[i] = 0.f;
}

extern "C" void kernel_launch(void* const* d_in, const int* in_sizes, int n_in,
                              void* d_out, int out_size)
{
    const float* x  = (const float*)d_in[0];
    const float* Wq = (const float*)d_in[1];
    const float* bq = (const float*)d_in[2];
    const float* Wk = (const float*)d_in[3];
    const float* bk = (const float*)d_in[4];
    const float* Wv = (const float*)d_in[5];
    const float* bv = (const float*)d_in[6];
    const float* Wo = (const float*)d_in[7];
    const float* bo = (const float*)d_in[8];
    const float* Wf = (const float*)d_in[9];
    const float* bff = (const float*)d_in[10];
    float* out = (float*)d_out;

    float *dQ, *dK, *dVt, *dP, *dA, *dO, *dXr, *dWr;
    cudaGetSymbolAddress((void**)&dQ, g_Q);
    cudaGetSymbolAddress((void**)&dK, g_K);
    cudaGetSymbolAddress((void**)&dVt, g_Vt);
    cudaGetSymbolAddress((void**)&dP, g_P);
    cudaGetSymbolAddress((void**)&dA, g_Attn);
    cudaGetSymbolAddress((void**)&dO, g_O);
    cudaGetSymbolAddress((void**)&dXr, g_Xr);
    cudaGetSymbolAddress((void**)&dWr, g_Wr);
    float* dWqr = dWr;
    float* dWkr = dWr + 1024 * 1024;
    float* dWvr = dWr + 2 * 1024 * 1024;
    float* dWor = dWr + 3 * 1024 * 1024;
    float* dWfr = dWr + 4 * 1024 * 1024;

    cudaFuncSetAttribute(gemm_qkv,
                         cudaFuncAttributeMaxDynamicSharedMemorySize, SMEM_BYTES);
    cudaFuncSetAttribute(gemm_tf32<0, true, false, false>,
                         cudaFuncAttributeMaxDynamicSharedMemorySize, SMEM_BYTES);
    cudaFuncSetAttribute(gemm_tf32<0, false, true, true>,
                         cudaFuncAttributeMaxDynamicSharedMemorySize, SMEM_BYTES);
    cudaFuncSetAttribute(gemm_tf32<1, false, false, true>,
                         cudaFuncAttributeMaxDynamicSharedMemorySize, SMEM_BYTES);
    cudaFuncSetAttribute(gemm_tf32<2, false, false, false>,
                         cudaFuncAttributeMaxDynamicSharedMemorySize, SMEM_BYTES);

    dim3 blk(NTHREADS);
    dim3 blk256(256);

    // merged tf32 rounding pre-pass (x + 5 weight matrices, one launch)
    round_all<<<dim3(128, 6), blk256>>>(x, dXr, Wq, dWqr, Wk, dWkr,
                                        Wv, dWvr, Wo, dWor, Wf, dWfr);

    // fused Q/K/V projections (Q pre-scaled by 2^-5; V transposed)
    gemm_qkv<<<dim3(8, 64, 3), blk, SMEM_BYTES>>>(
        dXr, dWqr, dWkr, dWvr, bq, bk, bv, dQ, dK, dVt);

    // scores = Qs K^T (already scaled), causal tile skip
    dim3 gS(16, 16, 4);
    gemm_tf32<0, true, false, false><<<gS, blk, SMEM_BYTES>>>(
        dQ, dK, nullptr, dP, 1024, 1024, 1024, 2048,
        2048LL * 1024, 2048LL * 1024, 2048LL * 2048, 1.f);

    softmax_causal<<<dim3(2048, 4), blk256>>>(dP, 2048);

    // attn = P @ Vt^T with causal K-trim, LPT (heavy bm first)
    dim3 gA(8, 16, 4);
    gemm_tf32<0, false, true, true><<<gA, blk, SMEM_BYTES>>>(
        dP, dVt, nullptr, dA, 2048, 2048, 8192, 1024,
        2048LL * 2048, 2048LL, 2048LL * 1024, 1.f);

    // O projection (rounded, feeds FFN)
    dim3 gProj(8, 64, 1);
    gemm_tf32<1, false, false, true><<<gProj, blk, SMEM_BYTES>>>(
        dA, dWor, bo, dO, 1024, 1024, 1024, 1024, 0, 0, 0, 1.f);

    // FFN + exact GELU -> d_out
    dim3 gF(32, 64, 1);
    gemm_tf32<2, false, false, false><<<gF, blk, SMEM_BYTES>>>(
        dO, dWfr, bff, out, 1024, 1024, 1024, 4096, 0, 0, 0, 1.f);
}

// round 16
// speedup vs baseline: 4.9230x; 1.7704x over previous
#include <cuda_runtime.h>
#include <cuda_fp16.h>
#include <cmath>
#include <cstdint>

// ---------------------------------------------------------------------------
// DecoderBlock, sm_103 family: fp16 mma.sync.m16n8k16 (fp32 accum),
// cp.async 3-stage ring (K=64 per 32KB stage), one barrier per stage.
// Operands pre-converted to fp16 in gmem; SCORES kept fp32 (softmax reads
// fp32, emits fp16 P). 64x64 warp tiles; CTA 128x128, 128 threads.
// smem elem (r,k): byte r*128 + ((k>>3)^(r&7))*16 + (k&7)*2  (conflict-free).
// ---------------------------------------------------------------------------

#define BM 128
#define BN 128
#define BKT 64
#define NTHREADS 128
#define STAGE_BYTES 32768
#define SMEM_BYTES (3 * STAGE_BYTES)

__device__ __half g_Qh[8192 * 1024];
__device__ __half g_Kh[8192 * 1024];
__device__ __half g_Vth[1024 * 8192];
__device__ float  g_S[4 * 2048 * 2048];     // fp32 scores
__device__ __half g_Ph[4 * 2048 * 2048];    // fp16 probs
__device__ __half g_Ah[8192 * 1024];
__device__ __half g_Oh[8192 * 1024];
__device__ __half g_Xh[8192 * 1024];
__device__ __half g_Wh[8 * 1024 * 1024];    // Wq,Wk,Wv,Wo (1M each), Wf (4M)

__device__ __forceinline__ uint32_t s2u(const void* p) {
    uint32_t a;
    asm("{ .reg .u64 t; cvta.to.shared.u64 t, %1; cvt.u32.u64 %0, t; }"
        : "=r"(a) : "l"(p));
    return a;
}

__device__ __forceinline__ void mma16(float* c, const unsigned* a, const unsigned* b) {
    asm volatile(
        "mma.sync.aligned.m16n8k16.row.col.f32.f16.f16.f32 "
        "{%0,%1,%2,%3}, {%4,%5,%6,%7}, {%8,%9}, {%0,%1,%2,%3};\n"
        : "+f"(c[0]), "+f"(c[1]), "+f"(c[2]), "+f"(c[3])
        : "r"(a[0]), "r"(a[1]), "r"(a[2]), "r"(a[3]), "r"(b[0]), "r"(b[1]));
}

#define CP16(dst, src) \
    asm volatile("cp.async.cg.shared.global [%0], [%1], 16;" :: "r"(dst), "l"(src))
#define CP_COMMIT() asm volatile("cp.async.commit_group;")
#define CP_WAIT1() asm volatile("cp.async.wait_group 1;")
#define CP_WAIT0() asm volatile("cp.async.wait_group 0;")

__device__ __forceinline__ float gelu_exact(float v) {
    return 0.5f * v * (1.0f + erff(v * 0.70710678118654752f));
}

// ---- mainloop: 2x2 warp grid, 64x64 warp tiles, fp16 operands --------------
struct FragCtx {
    int wm, wn2, g, tig;
};

__device__ __forceinline__ void ld_frags(
    const __half* a_s, const __half* b_s, int kk, const FragCtx& fc,
    unsigned af[4][4], unsigned bfr[8][2])
{
    const int j0 = kk >> 3;                  // even (kk multiple of 16)
    const unsigned ho = ((unsigned)(j0 ^ fc.g) << 3) + 2 * fc.tig;
#pragma unroll
    for (int im = 0; im < 4; im++) {
        const int m0 = fc.wm * 64 + im * 16 + fc.g;
        const __half* p = a_s + m0 * 64;
        af[im][0] = *(const unsigned*)(p + ho);
        af[im][1] = *(const unsigned*)(p + 8 * 64 + ho);
        af[im][2] = *(const unsigned*)(p + (ho ^ 8));
        af[im][3] = *(const unsigned*)(p + 8 * 64 + (ho ^ 8));
    }
#pragma unroll
    for (int in = 0; in < 8; in++) {
        const int n0 = fc.wn2 * 64 + in * 8 + fc.g;
        const __half* p = b_s + n0 * 64;
        bfr[in][0] = *(const unsigned*)(p + ho);
        bfr[in][1] = *(const unsigned*)(p + (ho ^ 8));
    }
}

__device__ __forceinline__ void mainloop(
    const __half* __restrict__ Arow, const __half* __restrict__ Brow,
    int lda, int ldb, int nT, char* smem, uint32_t sbase,
    const FragCtx& fc, float acc[4][8][4])
{
    const int tid = threadIdx.x;
    auto issue = [&](int t) {
        const int s = t % 3;
        const int k0 = t * BKT;
        const uint32_t dA = sbase + s * STAGE_BYTES;
        const uint32_t dB = dA + 16384;
#pragma unroll
        for (int i = 0; i < 8; i++) {
            const int gi = i * 128 + tid;    // 0..1023
            const int r = gi >> 3, j = gi & 7;
            const uint32_t off = r * 128 + ((j ^ (r & 7)) << 4);
            CP16(dA + off, Arow + (size_t)r * lda + k0 + j * 8);
            CP16(dB + off, Brow + (size_t)r * ldb + k0 + j * 8);
        }
        CP_COMMIT();
    };

    issue(0);
    if (nT > 1) issue(1);

    unsigned af[2][4][4], bfr[2][8][2];

    for (int t = 0; t < nT; ++t) {
        if (t < nT - 1) CP_WAIT1(); else CP_WAIT0();
        __syncthreads();
        if (t + 2 < nT) issue(t + 2);

        const __half* a_s = (const __half*)(smem + (t % 3) * STAGE_BYTES);
        const __half* b_s = (const __half*)(smem + (t % 3) * STAGE_BYTES + 16384);

        ld_frags(a_s, b_s, 0, fc, af[0], bfr[0]);
#pragma unroll
        for (int kk = 0; kk < BKT; kk += 16) {
            const int cur = (kk >> 4) & 1;
            if (kk + 16 < BKT)
                ld_frags(a_s, b_s, kk + 16, fc, af[cur ^ 1], bfr[cur ^ 1]);
#pragma unroll
            for (int im = 0; im < 4; im++)
#pragma unroll
                for (int in = 0; in < 8; in++)
                    mma16(acc[im][in], af[cur][im], bfr[cur][in]);
        }
    }
}

// ---- generic GEMM ----------------------------------------------------------
// EPI: 0 = alpha*acc ; 1 = acc+bias ; 2 = gelu(acc+bias) ; 3 = transposed acc+bias
// HOUT: store __half, else float.  LIMITK reverses bm (LPT) and trims K.
template <int EPI, bool CAUSAL, bool LIMITK, bool HOUT>
__global__ void __launch_bounds__(NTHREADS, 2) gemm_f16(
    const __half* __restrict__ A, const __half* __restrict__ B,
    const float* __restrict__ bias, void* __restrict__ Cv,
    int K, int lda, int ldb, int ldc,
    long long strA, long long strB, long long strC, float alpha)
{
    extern __shared__ char smem[];
    const uint32_t sbase = s2u(smem);

    const int bm = LIMITK ? (gridDim.y - 1 - blockIdx.y) : blockIdx.y;
    const int bn = blockIdx.x;
    if (CAUSAL && bn * BN > bm * BM + (BM - 1)) return;
    A += (long long)blockIdx.z * strA;
    B += (long long)blockIdx.z * strB;
    const int nT = LIMITK ? (bm + 1) * (128 / BKT) : (K / BKT);

    const int tid = threadIdx.x;
    const int warp = tid >> 5, lane = tid & 31;
    FragCtx fc;
    fc.wm = warp & 1; fc.wn2 = warp >> 1;
    fc.g = lane >> 2; fc.tig = lane & 3;

    float acc[4][8][4];
#pragma unroll
    for (int i = 0; i < 4; i++)
#pragma unroll
        for (int j = 0; j < 8; j++)
#pragma unroll
            for (int k = 0; k < 4; k++) acc[i][j][k] = 0.f;

    mainloop(A + (size_t)(bm * BM) * lda, B + (size_t)(bn * BN) * ldb,
             lda, ldb, nT, smem, sbase, fc, acc);

#pragma unroll
    for (int im = 0; im < 4; im++) {
        const int r0 = bm * BM + fc.wm * 64 + im * 16 + fc.g;
#pragma unroll
        for (int in = 0; in < 8; in++) {
            const int c0 = bn * BN + fc.wn2 * 64 + in * 8 + fc.tig * 2;
            float v00 = acc[im][in][0], v01 = acc[im][in][1];
            float v10 = acc[im][in][2], v11 = acc[im][in][3];
            if (EPI == 0) {
                v00 *= alpha; v01 *= alpha; v10 *= alpha; v11 *= alpha;
            } else {
                const float b0 = bias[c0], b1 = bias[c0 + 1];
                v00 += b0; v01 += b1; v10 += b0; v11 += b1;
                if (EPI == 2) {
                    v00 = gelu_exact(v00); v01 = gelu_exact(v01);
                    v10 = gelu_exact(v10); v11 = gelu_exact(v11);
                }
            }
            if (HOUT) {
                __half* C = (__half*)Cv + (long long)blockIdx.z * strC;
                if (EPI == 3) {
                    C[(size_t)c0 * ldc + r0] = __float2half(v00);
                    C[(size_t)(c0 + 1) * ldc + r0] = __float2half(v01);
                    C[(size_t)c0 * ldc + r0 + 8] = __float2half(v10);
                    C[(size_t)(c0 + 1) * ldc + r0 + 8] = __float2half(v11);
                } else {
                    *(__half2*)(C + (size_t)r0 * ldc + c0) = __floats2half2_rn(v00, v01);
                    *(__half2*)(C + (size_t)(r0 + 8) * ldc + c0) = __floats2half2_rn(v10, v11);
                }
            } else {
                float* C = (float*)Cv + (long long)blockIdx.z * strC;
                *(float2*)(C + (size_t)r0 * ldc + c0) = make_float2(v00, v01);
                *(float2*)(C + (size_t)(r0 + 8) * ldc + c0) = make_float2(v10, v11);
            }
        }
    }
}

// ---- fused Q/K/V projection (z = 0:Q scaled 2^-5, 1:K, 2:V transposed) -----
__global__ void __launch_bounds__(NTHREADS, 2) gemm_qkv(
    const __half* __restrict__ X,
    const __half* __restrict__ Wq, const __half* __restrict__ Wk,
    const __half* __restrict__ Wv,
    const float* __restrict__ bq, const float* __restrict__ bk,
    const float* __restrict__ bv,
    __half* __restrict__ Q, __half* __restrict__ Ko, __half* __restrict__ Vt)
{
    extern __shared__ char smem[];
    const uint32_t sbase = s2u(smem);

    const int bm = blockIdx.y, bn = blockIdx.x, z = blockIdx.z;
    const __half* W = (z == 0) ? Wq : (z == 1 ? Wk : Wv);
    const float* bias = (z == 0) ? bq : (z == 1 ? bk : bv);
    const float alpha = (z == 0) ? 0.03125f : 1.0f;

    const int tid = threadIdx.x;
    const int warp = tid >> 5, lane = tid & 31;
    FragCtx fc;
    fc.wm = warp & 1; fc.wn2 = warp >> 1;
    fc.g = lane >> 2; fc.tig = lane & 3;

    float acc[4][8][4];
#pragma unroll
    for (int i = 0; i < 4; i++)
#pragma unroll
        for (int j = 0; j < 8; j++)
#pragma unroll
            for (int k = 0; k < 4; k++) acc[i][j][k] = 0.f;

    mainloop(X + (size_t)(bm * BM) * 1024, W + (size_t)(bn * BN) * 1024,
             1024, 1024, 1024 / BKT, smem, sbase, fc, acc);

#pragma unroll
    for (int im = 0; im < 4; im++) {
        const int r0 = bm * BM + fc.wm * 64 + im * 16 + fc.g;
#pragma unroll
        for (int in = 0; in < 8; in++) {
            const int c0 = bn * BN + fc.wn2 * 64 + in * 8 + fc.tig * 2;
            const float b0 = bias[c0], b1 = bias[c0 + 1];
            float v00 = (acc[im][in][0] + b0) * alpha;
            float v01 = (acc[im][in][1] + b1) * alpha;
            float v10 = (acc[im][in][2] + b0) * alpha;
            float v11 = (acc[im][in][3] + b1) * alpha;
            if (z == 2) {
                Vt[(size_t)c0 * 8192 + r0] = __float2half(v00);
                Vt[(size_t)(c0 + 1) * 8192 + r0] = __float2half(v01);
                Vt[(size_t)c0 * 8192 + r0 + 8] = __float2half(v10);
                Vt[(size_t)(c0 + 1) * 8192 + r0 + 8] = __float2half(v11);
            } else {
                __half* C = (z == 0) ? Q : Ko;
                *(__half2*)(C + (size_t)r0 * 1024 + c0) = __floats2half2_rn(v00, v01);
                *(__half2*)(C + (size_t)(r0 + 8) * 1024 + c0) = __floats2half2_rn(v10, v11);
            }
        }
    }
}

// ---- merged fp16 conversion pre-pass (one launch, blockIdx.y = segment) ----
__global__ void round_all(
    const float* __restrict__ x,  __half* __restrict__ xo,
    const float* __restrict__ w0, __half* __restrict__ o0,
    const float* __restrict__ w1, __half* __restrict__ o1,
    const float* __restrict__ w2, __half* __restrict__ o2,
    const float* __restrict__ w3, __half* __restrict__ o3,
    const float* __restrict__ w4, __half* __restrict__ o4)
{
    const int seg = blockIdx.y;
    const float* in;
    __half* out;
    long long n4;
    if (seg == 0)      { in = x;  out = xo; n4 = 8192LL * 1024 / 4; }
    else if (seg == 1) { in = w0; out = o0; n4 = 1024LL * 1024 / 4; }
    else if (seg == 2) { in = w1; out = o1; n4 = 1024LL * 1024 / 4; }
    else if (seg == 3) { in = w2; out = o2; n4 = 1024LL * 1024 / 4; }
    else if (seg == 4) { in = w3; out = o3; n4 = 1024LL * 1024 / 4; }
    else               { in = w4; out = o4; n4 = 4096LL * 1024 / 4; }

    long long i = (long long)blockIdx.x * blockDim.x + threadIdx.x;
    long long stride = (long long)gridDim.x * blockDim.x;
    for (; i < n4; i += stride) {
        float4 v = ((const float4*)in)[i];
        __half2 h0 = __floats2half2_rn(v.x, v.y);
        __half2 h1 = __floats2half2_rn(v.z, v.w);
        ((__half2*)out)[2 * i] = h0;
        ((__half2*)out)[2 * i + 1] = h1;
    }
}

// Row-wise causal softmax: reads fp32 scores, writes fp16 probs; zero-fills
// the fp16 row up to the 128-aligned block end (all P@V's LIMITK reads).
__global__ void softmax_causal(const float* __restrict__ S,
                               __half* __restrict__ P, int len) {
    __shared__ float buf[2048];
    __shared__ float red[33];
    const int q = blockIdx.x, b = blockIdx.y;
    const float* row = S + ((size_t)b * len + q) * (size_t)len;
    __half* rowo = P + ((size_t)b * len + q) * (size_t)len;
    const int n = q + 1;
    const int tid = threadIdx.x;

    float m = -3.4e38f;
    for (int i = tid; i < n; i += 256) { float v = row[i]; buf[i] = v; m = fmaxf(m, v); }
#pragma unroll
    for (int o = 16; o; o >>= 1) m = fmaxf(m, __shfl_xor_sync(0xffffffff, m, o));
    if ((tid & 31) == 0) red[tid >> 5] = m;
    __syncthreads();
    if (tid == 0) {
        float v = -3.4e38f;
        for (int i = 0; i < 8; i++) v = fmaxf(v, red[i]);
        red[32] = v;
    }
    __syncthreads();
    m = red[32];

    float s = 0.f;
    for (int i = tid; i < n; i += 256) { float e = __expf(buf[i] - m); buf[i] = e; s += e; }
#pragma unroll
    for (int o = 16; o; o >>= 1) s += __shfl_xor_sync(0xffffffff, s, o);
    if ((tid & 31) == 0) red[tid >> 5] = s;
    __syncthreads();
    if (tid == 0) {
        float v = 0.f;
        for (int i = 0; i < 8; i++) v += red[i];
        red[32] = 1.0f / v;
    }
    __syncthreads();
    const float inv = red[32];

    for (int i = tid; i < n; i += 256) rowo[i] = __float2half(buf[i] * inv);
    const int zend = min(len, ((q >> 7) + 1) << 7);
    for (int i = n + tid; i < zend; i += 256) rowo[i] = __float2half(0.f);
}

extern "C" void kernel_launch(void* const* d_in, const int* in_sizes, int n_in,
                              void* d_out, int out_size)
{
    const float* x  = (const float*)d_in[0];
    const float* Wq = (const float*)d_in[1];
    const float* bq = (const float*)d_in[2];
    const float* Wk = (const float*)d_in[3];
    const float* bk = (const float*)d_in[4];
    const float* Wv = (const float*)d_in[5];
    const float* bv = (const float*)d_in[6];
    const float* Wo = (const float*)d_in[7];
    const float* bo = (const float*)d_in[8];
    const float* Wf = (const float*)d_in[9];
    const float* bff = (const float*)d_in[10];
    float* out = (float*)d_out;

    __half *dQ, *dK, *dVt, *dPh, *dA, *dO, *dXh, *dWh;
    float* dS;
    cudaGetSymbolAddress((void**)&dQ, g_Qh);
    cudaGetSymbolAddress((void**)&dK, g_Kh);
    cudaGetSymbolAddress((void**)&dVt, g_Vth);
    cudaGetSymbolAddress((void**)&dS, g_S);
    cudaGetSymbolAddress((void**)&dPh, g_Ph);
    cudaGetSymbolAddress((void**)&dA, g_Ah);
    cudaGetSymbolAddress((void**)&dO, g_Oh);
    cudaGetSymbolAddress((void**)&dXh, g_Xh);
    cudaGetSymbolAddress((void**)&dWh, g_Wh);
    __half* dWqh = dWh;
    __half* dWkh = dWh + 1024 * 1024;
    __half* dWvh = dWh + 2 * 1024 * 1024;
    __half* dWoh = dWh + 3 * 1024 * 1024;
    __half* dWfh = dWh + 4 * 1024 * 1024;

    cudaFuncSetAttribute(gemm_qkv,
                         cudaFuncAttributeMaxDynamicSharedMemorySize, SMEM_BYTES);
    cudaFuncSetAttribute(gemm_f16<0, true, false, false>,
                         cudaFuncAttributeMaxDynamicSharedMemorySize, SMEM_BYTES);
    cudaFuncSetAttribute(gemm_f16<0, false, true, true>,
                         cudaFuncAttributeMaxDynamicSharedMemorySize, SMEM_BYTES);
    cudaFuncSetAttribute(gemm_f16<1, false, false, true>,
                         cudaFuncAttributeMaxDynamicSharedMemorySize, SMEM_BYTES);
    cudaFuncSetAttribute(gemm_f16<2, false, false, false>,
                         cudaFuncAttributeMaxDynamicSharedMemorySize, SMEM_BYTES);

    dim3 blk(NTHREADS);
    dim3 blk256(256);

    // fp16 conversion pre-pass (x + 5 weight matrices, one launch)
    round_all<<<dim3(128, 6), blk256>>>(x, dXh, Wq, dWqh, Wk, dWkh,
                                        Wv, dWvh, Wo, dWoh, Wf, dWfh);

    // fused Q/K/V projections (Q pre-scaled by 2^-5; V transposed)
    gemm_qkv<<<dim3(8, 64, 3), blk, SMEM_BYTES>>>(
        dXh, dWqh, dWkh, dWvh, bq, bk, bv, dQ, dK, dVt);

    // scores = Qs K^T (already scaled) -> fp32, causal tile skip
    dim3 gS(16, 16, 4);
    gemm_f16<0, true, false, false><<<gS, blk, SMEM_BYTES>>>(
        dQ, dK, nullptr, dS, 1024, 1024, 1024, 2048,
        2048LL * 1024, 2048LL * 1024, 2048LL * 2048, 1.f);

    softmax_causal<<<dim3(2048, 4), blk256>>>(dS, dPh, 2048);

    // attn = P @ Vt^T with causal K-trim, LPT (heavy bm first) -> fp16
    dim3 gA(8, 16, 4);
    gemm_f16<0, false, true, true><<<gA, blk, SMEM_BYTES>>>(
        dPh, dVt, nullptr, dA, 2048, 2048, 8192, 1024,
        2048LL * 2048, 2048LL, 2048LL * 1024, 1.f);

    // O projection -> fp16 (feeds FFN)
    dim3 gProj(8, 64, 1);
    gemm_f16<1, false, false, true><<<gProj, blk, SMEM_BYTES>>>(
        dA, dWoh, bo, dO, 1024, 1024, 1024, 1024, 0, 0, 0, 1.f);

    // FFN + exact GELU -> fp32 d_out
    dim3 gF(32, 64, 1);
    gemm_f16<2, false, false, false><<<gF, blk, SMEM_BYTES>>>(
        dO, dWfh, bff, out, 1024, 1024, 1024, 4096, 0, 0, 0, 1.f);
}

// round 17
// speedup vs baseline: 5.2210x; 1.0605x over previous
#include <cuda_runtime.h>
#include <cuda_fp16.h>
#include <cmath>
#include <cstdint>

// ---------------------------------------------------------------------------
// DecoderBlock, sm_103 family: fp16 mma.sync.m16n8k16 (fp32 accum),
// cp.async 3-stage ring (K=64 per 32KB stage), one barrier per stage.
// R17: ldmatrix.m8n8.x4 fragment loads — 8 LDSM replace 32 LDS per kk16.
// Operands pre-converted fp16; scores fp32; softmax emits fp16 P.
// 64x64 warp tiles; CTA 128x128, 128 threads.
// smem elem (r,k): byte r*128 + ((k>>3)^(r&7))*16 + (k&7)*2  (conflict-free).
// ---------------------------------------------------------------------------

#define BM 128
#define BN 128
#define BKT 64
#define NTHREADS 128
#define STAGE_BYTES 32768
#define SMEM_BYTES (3 * STAGE_BYTES)

__device__ __half g_Qh[8192 * 1024];
__device__ __half g_Kh[8192 * 1024];
__device__ __half g_Vth[1024 * 8192];
__device__ float  g_S[4 * 2048 * 2048];
__device__ __half g_Ph[4 * 2048 * 2048];
__device__ __half g_Ah[8192 * 1024];
__device__ __half g_Oh[8192 * 1024];
__device__ __half g_Xh[8192 * 1024];
__device__ __half g_Wh[8 * 1024 * 1024];

__device__ __forceinline__ uint32_t s2u(const void* p) {
    uint32_t a;
    asm("{ .reg .u64 t; cvta.to.shared.u64 t, %1; cvt.u32.u64 %0, t; }"
        : "=r"(a) : "l"(p));
    return a;
}

__device__ __forceinline__ void mma16(float* c, const unsigned* a, const unsigned* b) {
    asm volatile(
        "mma.sync.aligned.m16n8k16.row.col.f32.f16.f16.f32 "
        "{%0,%1,%2,%3}, {%4,%5,%6,%7}, {%8,%9}, {%0,%1,%2,%3};\n"
        : "+f"(c[0]), "+f"(c[1]), "+f"(c[2]), "+f"(c[3])
        : "r"(a[0]), "r"(a[1]), "r"(a[2]), "r"(a[3]), "r"(b[0]), "r"(b[1]));
}

#define LDSM4(r0, r1, r2, r3, addr)                                          \
    asm volatile("ldmatrix.sync.aligned.m8n8.x4.shared.b16 {%0,%1,%2,%3}, [%4];" \
        : "=r"(r0), "=r"(r1), "=r"(r2), "=r"(r3) : "r"(addr))

#define CP16(dst, src) \
    asm volatile("cp.async.cg.shared.global [%0], [%1], 16;" :: "r"(dst), "l"(src))
#define CP_COMMIT() asm volatile("cp.async.commit_group;")
#define CP_WAIT1() asm volatile("cp.async.wait_group 1;")
#define CP_WAIT0() asm volatile("cp.async.wait_group 0;")

__device__ __forceinline__ float gelu_exact(float v) {
    return 0.5f * v * (1.0f + erff(v * 0.70710678118654752f));
}

// ---- mainloop: 2x2 warp grid, 64x64 warp tiles, ldmatrix fragment loads ----
struct FragCtx {
    int wm, wn2, g, tig, lane;
};

__device__ __forceinline__ void ld_frags(
    uint32_t a_su, uint32_t b_su, int kk, const FragCtx& fc,
    unsigned af[4][4], unsigned bfr[8][2])
{
    const int l = fc.lane;
    const int lr = l & 7;
    const int lh8 = (l >> 3) & 1;
    const int lh16 = (l >> 4) & 1;
    const int j0 = kk >> 3;        // even
#pragma unroll
    for (int im = 0; im < 4; im++) {
        const int rowA = fc.wm * 64 + im * 16 + lr + lh8 * 8;
        const uint32_t addr =
            a_su + rowA * 128 + ((unsigned)((j0 + lh16) ^ (rowA & 7)) << 4);
        LDSM4(af[im][0], af[im][1], af[im][2], af[im][3], addr);
    }
#pragma unroll
    for (int p = 0; p < 4; p++) {
        const int rowB = fc.wn2 * 64 + (2 * p + lh16) * 8 + lr;
        const uint32_t addr =
            b_su + rowB * 128 + ((unsigned)((j0 + lh8) ^ (rowB & 7)) << 4);
        LDSM4(bfr[2 * p][0], bfr[2 * p][1], bfr[2 * p + 1][0], bfr[2 * p + 1][1],
              addr);
    }
}

__device__ __forceinline__ void mainloop(
    const __half* __restrict__ Arow, const __half* __restrict__ Brow,
    int lda, int ldb, int nT, uint32_t sbase,
    const FragCtx& fc, float acc[4][8][4])
{
    const int tid = threadIdx.x;
    auto issue = [&](int t) {
        const int s = t % 3;
        const int k0 = t * BKT;
        const uint32_t dA = sbase + s * STAGE_BYTES;
        const uint32_t dB = dA + 16384;
#pragma unroll
        for (int i = 0; i < 8; i++) {
            const int gi = i * 128 + tid;
            const int r = gi >> 3, j = gi & 7;
            const uint32_t off = r * 128 + ((j ^ (r & 7)) << 4);
            CP16(dA + off, Arow + (size_t)r * lda + k0 + j * 8);
            CP16(dB + off, Brow + (size_t)r * ldb + k0 + j * 8);
        }
        CP_COMMIT();
    };

    issue(0);
    if (nT > 1) issue(1);

    unsigned af[2][4][4], bfr[2][8][2];

    for (int t = 0; t < nT; ++t) {
        if (t < nT - 1) CP_WAIT1(); else CP_WAIT0();
        __syncthreads();
        if (t + 2 < nT) issue(t + 2);

        const uint32_t a_su = sbase + (t % 3) * STAGE_BYTES;
        const uint32_t b_su = a_su + 16384;

        ld_frags(a_su, b_su, 0, fc, af[0], bfr[0]);
#pragma unroll
        for (int kk = 0; kk < BKT; kk += 16) {
            const int cur = (kk >> 4) & 1;
            if (kk + 16 < BKT)
                ld_frags(a_su, b_su, kk + 16, fc, af[cur ^ 1], bfr[cur ^ 1]);
#pragma unroll
            for (int im = 0; im < 4; im++)
#pragma unroll
                for (int in = 0; in < 8; in++)
                    mma16(acc[im][in], af[cur][im], bfr[cur][in]);
        }
    }
}

// ---- generic GEMM ----------------------------------------------------------
// EPI: 0 = alpha*acc ; 1 = acc+bias ; 2 = gelu(acc+bias) ; 3 = transposed acc+bias
// HOUT: store __half, else float.  LIMITK reverses bm (LPT) and trims K.
template <int EPI, bool CAUSAL, bool LIMITK, bool HOUT>
__global__ void __launch_bounds__(NTHREADS, 2) gemm_f16(
    const __half* __restrict__ A, const __half* __restrict__ B,
    const float* __restrict__ bias, void* __restrict__ Cv,
    int K, int lda, int ldb, int ldc,
    long long strA, long long strB, long long strC, float alpha)
{
    extern __shared__ char smem[];
    const uint32_t sbase = s2u(smem);

    const int bm = LIMITK ? (gridDim.y - 1 - blockIdx.y) : blockIdx.y;
    const int bn = blockIdx.x;
    if (CAUSAL && bn * BN > bm * BM + (BM - 1)) return;
    A += (long long)blockIdx.z * strA;
    B += (long long)blockIdx.z * strB;
    const int nT = LIMITK ? (bm + 1) * (128 / BKT) : (K / BKT);

    const int tid = threadIdx.x;
    const int warp = tid >> 5, lane = tid & 31;
    FragCtx fc;
    fc.wm = warp & 1; fc.wn2 = warp >> 1;
    fc.g = lane >> 2; fc.tig = lane & 3; fc.lane = lane;

    float acc[4][8][4];
#pragma unroll
    for (int i = 0; i < 4; i++)
#pragma unroll
        for (int j = 0; j < 8; j++)
#pragma unroll
            for (int k = 0; k < 4; k++) acc[i][j][k] = 0.f;

    mainloop(A + (size_t)(bm * BM) * lda, B + (size_t)(bn * BN) * ldb,
             lda, ldb, nT, sbase, fc, acc);

#pragma unroll
    for (int im = 0; im < 4; im++) {
        const int r0 = bm * BM + fc.wm * 64 + im * 16 + fc.g;
#pragma unroll
        for (int in = 0; in < 8; in++) {
            const int c0 = bn * BN + fc.wn2 * 64 + in * 8 + fc.tig * 2;
            float v00 = acc[im][in][0], v01 = acc[im][in][1];
            float v10 = acc[im][in][2], v11 = acc[im][in][3];
            if (EPI == 0) {
                v00 *= alpha; v01 *= alpha; v10 *= alpha; v11 *= alpha;
            } else {
                const float b0 = bias[c0], b1 = bias[c0 + 1];
                v00 += b0; v01 += b1; v10 += b0; v11 += b1;
                if (EPI == 2) {
                    v00 = gelu_exact(v00); v01 = gelu_exact(v01);
                    v10 = gelu_exact(v10); v11 = gelu_exact(v11);
                }
            }
            if (HOUT) {
                __half* C = (__half*)Cv + (long long)blockIdx.z * strC;
                if (EPI == 3) {
                    C[(size_t)c0 * ldc + r0] = __float2half(v00);
                    C[(size_t)(c0 + 1) * ldc + r0] = __float2half(v01);
                    C[(size_t)c0 * ldc + r0 + 8] = __float2half(v10);
                    C[(size_t)(c0 + 1) * ldc + r0 + 8] = __float2half(v11);
                } else {
                    *(__half2*)(C + (size_t)r0 * ldc + c0) = __floats2half2_rn(v00, v01);
                    *(__half2*)(C + (size_t)(r0 + 8) * ldc + c0) = __floats2half2_rn(v10, v11);
                }
            } else {
                float* C = (float*)Cv + (long long)blockIdx.z * strC;
                *(float2*)(C + (size_t)r0 * ldc + c0) = make_float2(v00, v01);
                *(float2*)(C + (size_t)(r0 + 8) * ldc + c0) = make_float2(v10, v11);
            }
        }
    }
}

// ---- fused Q/K/V projection (z = 0:Q scaled 2^-5, 1:K, 2:V transposed) -----
__global__ void __launch_bounds__(NTHREADS, 2) gemm_qkv(
    const __half* __restrict__ X,
    const __half* __restrict__ Wq, const __half* __restrict__ Wk,
    const __half* __restrict__ Wv,
    const float* __restrict__ bq, const float* __restrict__ bk,
    const float* __restrict__ bv,
    __half* __restrict__ Q, __half* __restrict__ Ko, __half* __restrict__ Vt)
{
    extern __shared__ char smem[];
    const uint32_t sbase = s2u(smem);

    const int bm = blockIdx.y, bn = blockIdx.x, z = blockIdx.z;
    const __half* W = (z == 0) ? Wq : (z == 1 ? Wk : Wv);
    const float* bias = (z == 0) ? bq : (z == 1 ? bk : bv);
    const float alpha = (z == 0) ? 0.03125f : 1.0f;

    const int tid = threadIdx.x;
    const int warp = tid >> 5, lane = tid & 31;
    FragCtx fc;
    fc.wm = warp & 1; fc.wn2 = warp >> 1;
    fc.g = lane >> 2; fc.tig = lane & 3; fc.lane = lane;

    float acc[4][8][4];
#pragma unroll
    for (int i = 0; i < 4; i++)
#pragma unroll
        for (int j = 0; j < 8; j++)
#pragma unroll
            for (int k = 0; k < 4; k++) acc[i][j][k] = 0.f;

    mainloop(X + (size_t)(bm * BM) * 1024, W + (size_t)(bn * BN) * 1024,
             1024, 1024, 1024 / BKT, sbase, fc, acc);

#pragma unroll
    for (int im = 0; im < 4; im++) {
        const int r0 = bm * BM + fc.wm * 64 + im * 16 + fc.g;
#pragma unroll
        for (int in = 0; in < 8; in++) {
            const int c0 = bn * BN + fc.wn2 * 64 + in * 8 + fc.tig * 2;
            const float b0 = bias[c0], b1 = bias[c0 + 1];
            float v00 = (acc[im][in][0] + b0) * alpha;
            float v01 = (acc[im][in][1] + b1) * alpha;
            float v10 = (acc[im][in][2] + b0) * alpha;
            float v11 = (acc[im][in][3] + b1) * alpha;
            if (z == 2) {
                Vt[(size_t)c0 * 8192 + r0] = __float2half(v00);
                Vt[(size_t)(c0 + 1) * 8192 + r0] = __float2half(v01);
                Vt[(size_t)c0 * 8192 + r0 + 8] = __float2half(v10);
                Vt[(size_t)(c0 + 1) * 8192 + r0 + 8] = __float2half(v11);
            } else {
                __half* C = (z == 0) ? Q : Ko;
                *(__half2*)(C + (size_t)r0 * 1024 + c0) = __floats2half2_rn(v00, v01);
                *(__half2*)(C + (size_t)(r0 + 8) * 1024 + c0) = __floats2half2_rn(v10, v11);
            }
        }
    }
}

// ---- merged fp16 conversion pre-pass ---------------------------------------
__global__ void round_all(
    const float* __restrict__ x,  __half* __restrict__ xo,
    const float* __restrict__ w0, __half* __restrict__ o0,
    const float* __restrict__ w1, __half* __restrict__ o1,
    const float* __restrict__ w2, __half* __restrict__ o2,
    const float* __restrict__ w3, __half* __restrict__ o3,
    const float* __restrict__ w4, __half* __restrict__ o4)
{
    const int seg = blockIdx.y;
    const float* in;
    __half* out;
    long long n4;
    if (seg == 0)      { in = x;  out = xo; n4 = 8192LL * 1024 / 4; }
    else if (seg == 1) { in = w0; out = o0; n4 = 1024LL * 1024 / 4; }
    else if (seg == 2) { in = w1; out = o1; n4 = 1024LL * 1024 / 4; }
    else if (seg == 3) { in = w2; out = o2; n4 = 1024LL * 1024 / 4; }
    else if (seg == 4) { in = w3; out = o3; n4 = 1024LL * 1024 / 4; }
    else               { in = w4; out = o4; n4 = 4096LL * 1024 / 4; }

    long long i = (long long)blockIdx.x * blockDim.x + threadIdx.x;
    long long stride = (long long)gridDim.x * blockDim.x;
    for (; i < n4; i += stride) {
        float4 v = ((const float4*)in)[i];
        __half2 h0 = __floats2half2_rn(v.x, v.y);
        __half2 h1 = __floats2half2_rn(v.z, v.w);
        ((__half2*)out)[2 * i] = h0;
        ((__half2*)out)[2 * i + 1] = h1;
    }
}

// Row-wise causal softmax: fp32 scores -> fp16 probs; zero-fills to block end.
__global__ void softmax_causal(const float* __restrict__ S,
                               __half* __restrict__ P, int len) {
    __shared__ float buf[2048];
    __shared__ float red[33];
    const int q = blockIdx.x, b = blockIdx.y;
    const float* row = S + ((size_t)b * len + q) * (size_t)len;
    __half* rowo = P + ((size_t)b * len + q) * (size_t)len;
    const int n = q + 1;
    const int tid = threadIdx.x;

    float m = -3.4e38f;
    for (int i = tid; i < n; i += 256) { float v = row[i]; buf[i] = v; m = fmaxf(m, v); }
#pragma unroll
    for (int o = 16; o; o >>= 1) m = fmaxf(m, __shfl_xor_sync(0xffffffff, m, o));
    if ((tid & 31) == 0) red[tid >> 5] = m;
    __syncthreads();
    if (tid == 0) {
        float v = -3.4e38f;
        for (int i = 0; i < 8; i++) v = fmaxf(v, red[i]);
        red[32] = v;
    }
    __syncthreads();
    m = red[32];

    float s = 0.f;
    for (int i = tid; i < n; i += 256) { float e = __expf(buf[i] - m); buf[i] = e; s += e; }
#pragma unroll
    for (int o = 16; o; o >>= 1) s += __shfl_xor_sync(0xffffffff, s, o);
    if ((tid & 31) == 0) red[tid >> 5] = s;
    __syncthreads();
    if (tid == 0) {
        float v = 0.f;
        for (int i = 0; i < 8; i++) v += red[i];
        red[32] = 1.0f / v;
    }
    __syncthreads();
    const float inv = red[32];

    for (int i = tid; i < n; i += 256) rowo[i] = __float2half(buf[i] * inv);
    const int zend = min(len, ((q >> 7) + 1) << 7);
    for (int i = n + tid; i < zend; i += 256) rowo[i] = __float2half(0.f);
}

extern "C" void kernel_launch(void* const* d_in, const int* in_sizes, int n_in,
                              void* d_out, int out_size)
{
    const float* x  = (const float*)d_in[0];
    const float* Wq = (const float*)d_in[1];
    const float* bq = (const float*)d_in[2];
    const float* Wk = (const float*)d_in[3];
    const float* bk = (const float*)d_in[4];
    const float* Wv = (const float*)d_in[5];
    const float* bv = (const float*)d_in[6];
    const float* Wo = (const float*)d_in[7];
    const float* bo = (const float*)d_in[8];
    const float* Wf = (const float*)d_in[9];
    const float* bff = (const float*)d_in[10];
    float* out = (float*)d_out;

    __half *dQ, *dK, *dVt, *dPh, *dA, *dO, *dXh, *dWh;
    float* dS;
    cudaGetSymbolAddress((void**)&dQ, g_Qh);
    cudaGetSymbolAddress((void**)&dK, g_Kh);
    cudaGetSymbolAddress((void**)&dVt, g_Vth);
    cudaGetSymbolAddress((void**)&dS, g_S);
    cudaGetSymbolAddress((void**)&dPh, g_Ph);
    cudaGetSymbolAddress((void**)&dA, g_Ah);
    cudaGetSymbolAddress((void**)&dO, g_Oh);
    cudaGetSymbolAddress((void**)&dXh, g_Xh);
    cudaGetSymbolAddress((void**)&dWh, g_Wh);
    __half* dWqh = dWh;
    __half* dWkh = dWh + 1024 * 1024;
    __half* dWvh = dWh + 2 * 1024 * 1024;
    __half* dWoh = dWh + 3 * 1024 * 1024;
    __half* dWfh = dWh + 4 * 1024 * 1024;

    cudaFuncSetAttribute(gemm_qkv,
                         cudaFuncAttributeMaxDynamicSharedMemorySize, SMEM_BYTES);
    cudaFuncSetAttribute(gemm_f16<0, true, false, false>,
                         cudaFuncAttributeMaxDynamicSharedMemorySize, SMEM_BYTES);
    cudaFuncSetAttribute(gemm_f16<0, false, true, true>,
                         cudaFuncAttributeMaxDynamicSharedMemorySize, SMEM_BYTES);
    cudaFuncSetAttribute(gemm_f16<1, false, false, true>,
                         cudaFuncAttributeMaxDynamicSharedMemorySize, SMEM_BYTES);
    cudaFuncSetAttribute(gemm_f16<2, false, false, false>,
                         cudaFuncAttributeMaxDynamicSharedMemorySize, SMEM_BYTES);

    dim3 blk(NTHREADS);
    dim3 blk256(256);

    // fp16 conversion pre-pass (x + 5 weight matrices, one launch)
    round_all<<<dim3(128, 6), blk256>>>(x, dXh, Wq, dWqh, Wk, dWkh,
                                        Wv, dWvh, Wo, dWoh, Wf, dWfh);

    // fused Q/K/V projections (Q pre-scaled by 2^-5; V transposed)
    gemm_qkv<<<dim3(8, 64, 3), blk, SMEM_BYTES>>>(
        dXh, dWqh, dWkh, dWvh, bq, bk, bv, dQ, dK, dVt);

    // scores = Qs K^T -> fp32, causal tile skip
    dim3 gS(16, 16, 4);
    gemm_f16<0, true, false, false><<<gS, blk, SMEM_BYTES>>>(
        dQ, dK, nullptr, dS, 1024, 1024, 1024, 2048,
        2048LL * 1024, 2048LL * 1024, 2048LL * 2048, 1.f);

    softmax_causal<<<dim3(2048, 4), blk256>>>(dS, dPh, 2048);

    // attn = P @ Vt^T with causal K-trim, LPT -> fp16
    dim3 gA(8, 16, 4);
    gemm_f16<0, false, true, true><<<gA, blk, SMEM_BYTES>>>(
        dPh, dVt, nullptr, dA, 2048, 2048, 8192, 1024,
        2048LL * 2048, 2048LL, 2048LL * 1024, 1.f);

    // O projection -> fp16 (feeds FFN)
    dim3 gProj(8, 64, 1);
    gemm_f16<1, false, false, true><<<gProj, blk, SMEM_BYTES>>>(
        dA, dWoh, bo, dO, 1024, 1024, 1024, 1024, 0, 0, 0, 1.f);

    // FFN + exact GELU -> fp32 d_out
    dim3 gF(32, 64, 1);
    gemm_f16<2, false, false, false><<<gF, blk, SMEM_BYTES>>>(
        dO, dWfh, bff, out, 1024, 1024, 1024, 4096, 0, 0, 0, 1.f);
}